// round 10
// baseline (speedup 1.0000x reference)
#include <cuda_runtime.h>
#include <cuda_fp16.h>
#include <mma.h>
using namespace nvcuda;

#define NH 16
#define HD 64
#define BB 2
#define TT 2048
#define SS 2048
#define EE 1024
#define MM (BB * TT)   // 4096 rows

// Scratch (allocation-free: device globals). Layout [B*T, E] = [b,t,h,d].
__device__ float  g_q[MM * EE];
__device__ float  g_k[MM * EE];     // tf32-rounded by gemm epilogue
__device__ __half g_v[MM * EE];     // fp16, by gemm epilogue
__device__ float  g_ctx[MM * EE];   // tf32-rounded by attn epilogue
__device__ float  g_rowinv[BB * NH * TT];

// tf32 pre-rounded copies of GEMM inputs (kills all in-loop F2FP converts)
__device__ float  r_src[MM * EE];
__device__ float  r_tgt[MM * EE];
__device__ float  r_wq[EE * EE];
__device__ float  r_wk[EE * EE];
__device__ float  r_wv[EE * EE];
__device__ float  r_wo[EE * EE];

// ---------------- helpers ----------------
__device__ __forceinline__ void cpa16(void* s, const void* g) {
    unsigned sa = (unsigned)__cvta_generic_to_shared(s);
    asm volatile("cp.async.ca.shared.global [%0], [%1], 16;\n" :: "r"(sa), "l"(g));
}
__device__ __forceinline__ void cp_commit() {
    asm volatile("cp.async.commit_group;\n");
}
template<int N> __device__ __forceinline__ void cp_wait() {
    asm volatile("cp.async.wait_group %0;\n" :: "n"(N));
}
__device__ __forceinline__ float ex2f(float x) {
    float y;
    asm("ex2.approx.f32 %0, %1;" : "=f"(y) : "f"(x));
    return y;
}
__device__ __forceinline__ void mma_tf32(float* c, unsigned a0, unsigned a1,
                                         unsigned a2, unsigned a3,
                                         unsigned b0, unsigned b1) {
    asm volatile(
        "mma.sync.aligned.m16n8k8.row.col.f32.tf32.tf32.f32 "
        "{%0,%1,%2,%3},{%4,%5,%6,%7},{%8,%9},{%0,%1,%2,%3};"
        : "+f"(c[0]), "+f"(c[1]), "+f"(c[2]), "+f"(c[3])
        : "r"(a0), "r"(a1), "r"(a2), "r"(a3), "r"(b0), "r"(b1));
}
__device__ __forceinline__ void mma_f16(float* c, unsigned a0, unsigned a1,
                                        unsigned a2, unsigned a3,
                                        unsigned b0, unsigned b1) {
    asm volatile(
        "mma.sync.aligned.m16n8k16.row.col.f32.f16.f16.f32 "
        "{%0,%1,%2,%3},{%4,%5,%6,%7},{%8,%9},{%0,%1,%2,%3};"
        : "+f"(c[0]), "+f"(c[1]), "+f"(c[2]), "+f"(c[3])
        : "r"(a0), "r"(a1), "r"(a2), "r"(a3), "r"(b0), "r"(b1));
}
__device__ __forceinline__ void ldsm_x4_t(unsigned& r0, unsigned& r1,
                                          unsigned& r2, unsigned& r3, unsigned addr) {
    asm volatile("ldmatrix.sync.aligned.m8n8.x4.trans.shared.b16 {%0,%1,%2,%3},[%4];"
                 : "=r"(r0), "=r"(r1), "=r"(r2), "=r"(r3) : "r"(addr));
}
__device__ __forceinline__ unsigned pack_h2(float lo, float hi) {
    __half2 h = __floats2half2_rn(lo, hi);
    return *(unsigned*)&h;
}

// ---------------------------------------------------------------------------
// Pre-round: out = tf32_rn(in). Pure streaming.
// ---------------------------------------------------------------------------
__global__ __launch_bounds__(256)
void round_kernel(const float4* __restrict__ in, float4* __restrict__ out, int n4)
{
    int i = blockIdx.x * blockDim.x + threadIdx.x;
    int stride = gridDim.x * blockDim.x;
    for (; i < n4; i += stride) {
        float4 v = in[i];
        v.x = wmma::__float_to_tf32(v.x);
        v.y = wmma::__float_to_tf32(v.y);
        v.z = wmma::__float_to_tf32(v.z);
        v.w = wmma::__float_to_tf32(v.w);
        out[i] = v;
    }
}

// ---------------------------------------------------------------------------
// NT GEMM (TF32 WMMA): C[M,N] = A[M,1024] * W[N,1024]^T
// Inputs are PRE-ROUNDED tf32 — no in-loop converts.
// BM=128, BN=128, BK=32, 256 threads, warp grid 4x2, warp tile 32x64.
// 2-stage cp.async double buffer.
// MODE: 0 = float raw (Q), 1 = float tf32-rounded (K), 2 = half (V),
//       3 = float + bias (output projection)
// ---------------------------------------------------------------------------

#define GLDA 36   // 32 + 4 pad

template<int MODE>
__device__ __forceinline__ void gemm_body(const float* __restrict__ A,
                                          const float* __restrict__ W,
                                          float* __restrict__ O,
                                          __half* __restrict__ Oh,
                                          const float* __restrict__ bo)
{
    __shared__ __align__(16) float smem_all[4 * 128 * GLDA];   // 73728 B
    float* As0 = smem_all;
    float* As1 = smem_all + 128 * GLDA;
    float* Ws0 = smem_all + 2 * 128 * GLDA;
    float* Ws1 = smem_all + 3 * 128 * GLDA;

    const int tid = threadIdx.x;
    const int warp = tid >> 5;
    const int wm = warp >> 1;
    const int wn = warp & 1;
    const int m0 = blockIdx.y * 128;
    const int n0 = blockIdx.x * 128;

    wmma::fragment<wmma::accumulator, 16, 16, 8, float> acc[2][4];
#pragma unroll
    for (int i = 0; i < 2; i++)
#pragma unroll
        for (int j = 0; j < 4; j++) wmma::fill_fragment(acc[i][j], 0.0f);

#pragma unroll
    for (int i = 0; i < 4; i++) {
        int e = tid + i * 256;
        int r = e >> 3, c = (e & 7) * 4;
        cpa16(As0 + r * GLDA + c, A + (size_t)(m0 + r) * 1024 + c);
        cpa16(Ws0 + r * GLDA + c, W + (size_t)(n0 + r) * 1024 + c);
    }
    cp_commit();

    for (int t = 0; t < 32; t++) {
        if (t < 31) {
            int k0 = (t + 1) * 32;
            float* ad = ((t + 1) & 1) ? As1 : As0;
            float* wd = ((t + 1) & 1) ? Ws1 : Ws0;
#pragma unroll
            for (int i = 0; i < 4; i++) {
                int e = tid + i * 256;
                int r = e >> 3, c = (e & 7) * 4;
                cpa16(ad + r * GLDA + c, A + (size_t)(m0 + r) * 1024 + k0 + c);
                cpa16(wd + r * GLDA + c, W + (size_t)(n0 + r) * 1024 + k0 + c);
            }
            cp_commit();
            cp_wait<1>();
        } else {
            cp_wait<0>();
        }
        __syncthreads();

        const float* as = (t & 1) ? As1 : As0;
        const float* ws = (t & 1) ? Ws1 : Ws0;
#pragma unroll
        for (int kk = 0; kk < 32; kk += 8) {
            wmma::fragment<wmma::matrix_a, 16, 16, 8, wmma::precision::tf32, wmma::row_major> af[2];
            wmma::fragment<wmma::matrix_b, 16, 16, 8, wmma::precision::tf32, wmma::col_major> bf[4];
#pragma unroll
            for (int i = 0; i < 2; i++)
                wmma::load_matrix_sync(af[i], as + (wm * 32 + i * 16) * GLDA + kk, GLDA);
#pragma unroll
            for (int j = 0; j < 4; j++)
                wmma::load_matrix_sync(bf[j], ws + (wn * 64 + j * 16) * GLDA + kk, GLDA);
#pragma unroll
            for (int i = 0; i < 2; i++)
#pragma unroll
                for (int j = 0; j < 4; j++)
                    wmma::mma_sync(acc[i][j], af[i], bf[j], acc[i][j]);
        }
        __syncthreads();
    }

    if (MODE == 3) {
        float* Cs = smem_all;      // 128 x 132
#pragma unroll
        for (int i = 0; i < 2; i++)
#pragma unroll
            for (int j = 0; j < 4; j++)
                wmma::store_matrix_sync(Cs + (wm * 32 + i * 16) * 132 + wn * 64 + j * 16,
                                        acc[i][j], 132, wmma::mem_row_major);
        __syncthreads();
#pragma unroll
        for (int i = 0; i < 16; i++) {
            int e = tid + i * 256;
            int r = e >> 5, c = (e & 31) * 4;
            float4 v = *(float4*)(Cs + r * 132 + c);
            float4 b4 = *(const float4*)(bo + n0 + c);
            v.x += b4.x; v.y += b4.y; v.z += b4.z; v.w += b4.w;
            *(float4*)(O + (size_t)(m0 + r) * EE + n0 + c) = v;
        }
    } else if (MODE == 2) {
        float* Cs = smem_all;
#pragma unroll
        for (int i = 0; i < 2; i++)
#pragma unroll
            for (int j = 0; j < 4; j++)
                wmma::store_matrix_sync(Cs + (wm * 32 + i * 16) * 132 + wn * 64 + j * 16,
                                        acc[i][j], 132, wmma::mem_row_major);
        __syncthreads();
#pragma unroll
        for (int i = 0; i < 16; i++) {
            int e = tid + i * 256;
            int r = e >> 5, c = (e & 31) * 4;
            float4 v = *(float4*)(Cs + r * 132 + c);
            __half2 h0 = __floats2half2_rn(v.x, v.y);
            __half2 h1 = __floats2half2_rn(v.z, v.w);
            unsigned u0 = *(unsigned*)&h0, u1 = *(unsigned*)&h1;
            uint2 pk = make_uint2(u0, u1);
            *(uint2*)(Oh + (size_t)(m0 + r) * EE + n0 + c) = pk;
        }
    } else {
        if (MODE == 1) {
#pragma unroll
            for (int i = 0; i < 2; i++)
#pragma unroll
                for (int j = 0; j < 4; j++)
#pragma unroll
                    for (int x = 0; x < acc[i][j].num_elements; x++)
                        acc[i][j].x[x] = wmma::__float_to_tf32(acc[i][j].x[x]);
        }
#pragma unroll
        for (int i = 0; i < 2; i++)
#pragma unroll
            for (int j = 0; j < 4; j++)
                wmma::store_matrix_sync(
                    O + (size_t)(m0 + wm * 32 + i * 16) * 1024 + n0 + wn * 64 + j * 16,
                    acc[i][j], 1024, wmma::mem_row_major);
    }
}

__global__ __launch_bounds__(256)
void gemm_qkv_kernel()
{
    const int z = blockIdx.z;
    if (z == 0)      gemm_body<0>(r_tgt, r_wq, g_q, nullptr, nullptr);
    else if (z == 1) gemm_body<1>(r_src, r_wk, g_k, nullptr, nullptr);
    else             gemm_body<2>(r_src, r_wv, nullptr, g_v, nullptr);
}

__global__ __launch_bounds__(256)
void gemm_out_kernel(const float* __restrict__ bo, float* __restrict__ out)
{
    gemm_body<3>(g_ctx, r_wo, out, nullptr, bo);
}

// ---------------------------------------------------------------------------
// Attention, register-resident P, single pass over keys.
// Each warp owns 16 query rows. Per 64-key tile:
//   QK via mma.m16n8k8.tf32; exp in regs (base-2); STS exp tile to smem;
//   PV via mma.m16n8k16.f16 (P packed from accumulators, V via ldmatrix.trans);
//   then coalesced STG.128 of the staged tile (4 lines/instr vs 8-row spread).
// Rowsum in regs -> g_rowinv; rescale_kernel normalizes attn afterwards.
// ---------------------------------------------------------------------------

#define KLD 68   // K tile row stride (floats)
#define VLD 72   // V tile row stride (halves)
#define SLD 68   // staged attn tile row stride (floats)

__global__ __launch_bounds__(256, 2)
void attn_kernel(float* __restrict__ attn_out)
{
    extern __shared__ __align__(16) float sm[];
    float*  K0 = sm;                            // 64*KLD floats
    float*  K1 = sm + 64 * KLD;
    __half* V0 = (__half*)(sm + 2 * 64 * KLD);  // 64*VLD halves
    __half* V1 = V0 + 64 * VLD;
    float*  Sb = sm + 2 * 64 * KLD + 64 * VLD;  // 128*SLD floats (staging)

    const int tid = threadIdx.x;
    const int warp = tid >> 5, lane = tid & 31;
    const int g = lane >> 2, tg = lane & 3;
    const int bh = blockIdx.y, b = bh >> 4, h = bh & 15;
    const int t0 = blockIdx.x * 128;

    const float*  kbase = g_k + (size_t)(b * SS) * EE + h * HD;
    const __half* vbase = g_v + (size_t)(b * SS) * EE + h * HD;

    // prologue: tile 0 loads in flight while Q loads run
#pragma unroll
    for (int i = 0; i < 4; i++) {
        int e = tid + i * 256, r = e >> 4, c = (e & 15) * 4;
        cpa16(K0 + r * KLD + c, kbase + (size_t)r * EE + c);
    }
#pragma unroll
    for (int i = 0; i < 2; i++) {
        int e = tid + i * 256, r = e >> 3, c = (e & 7) * 8;
        cpa16(V0 + r * VLD + c, vbase + (size_t)r * EE + c);
    }
    cp_commit();

    // Q into registers: rows (t0+16w+g) and (+8), cols tg+4i; scaled to base-2
    const float QSC = 1.44269504f * 0.125f;
    float qA[16], qB[16];
    {
        const float* qp = g_q + (size_t)(b * TT + t0 + warp * 16 + g) * EE + h * HD + tg;
#pragma unroll
        for (int i = 0; i < 16; i++) {
            qA[i] = wmma::__float_to_tf32(qp[4 * i] * QSC);
            qB[i] = wmma::__float_to_tf32(qp[(size_t)8 * EE + 4 * i] * QSC);
        }
    }

    float cacc[8][4];
#pragma unroll
    for (int j = 0; j < 8; j++)
#pragma unroll
        for (int x = 0; x < 4; x++) cacc[j][x] = 0.0f;
    float sumA = 0.0f, sumB = 0.0f;

    // staged-store coords: each thread stores half a row (32 cols = 8 float4)
    const int sr = tid >> 1;
    const int sc = (tid & 1) * 32;
    float* arow = attn_out + (size_t)(bh * TT + t0 + sr) * SS + sc;

    // STS coords for the exp tile
    float* sbA = Sb + (warp * 16 + g) * SLD;          // row (16w+g)
    float* sbB = sbA + 8 * SLD;                        // row (+8)

    for (int it = 0; it < 32; it++) {
        cp_wait<0>();
        __syncthreads();

        // prefetch tile it+1 into the other buffer
        if (it + 1 < 32) {
            float*  Kd = (it & 1) ? K0 : K1;
            __half* Vd = (it & 1) ? V0 : V1;
            const float*  ksrc = kbase + (size_t)(it + 1) * 64 * EE;
            const __half* vsrc = vbase + (size_t)(it + 1) * 64 * EE;
#pragma unroll
            for (int i = 0; i < 4; i++) {
                int e = tid + i * 256, r = e >> 4, c = (e & 15) * 4;
                cpa16(Kd + r * KLD + c, ksrc + (size_t)r * EE + c);
            }
#pragma unroll
            for (int i = 0; i < 2; i++) {
                int e = tid + i * 256, r = e >> 3, c = (e & 7) * 8;
                cpa16(Vd + r * VLD + c, vsrc + (size_t)r * EE + c);
            }
            cp_commit();
        }

        const float*  K = (it & 1) ? K1 : K0;
        const __half* V = (it & 1) ? V1 : V0;
        unsigned vaddr = (unsigned)__cvta_generic_to_shared(
            V + (lane & 15) * VLD + (lane >> 4) * 8);

#pragma unroll
        for (int jg = 0; jg < 4; jg++) {
            float S0[4] = {0, 0, 0, 0}, S1[4] = {0, 0, 0, 0};
            const float* Kb0 = K + (jg * 16 + g) * KLD + tg;
            const float* Kb1 = K + (jg * 16 + 8 + g) * KLD + tg;
#pragma unroll
            for (int ks = 0; ks < 8; ks++) {
                unsigned a0 = __float_as_uint(qA[2 * ks]);
                unsigned a1 = __float_as_uint(qB[2 * ks]);
                unsigned a2 = __float_as_uint(qA[2 * ks + 1]);
                unsigned a3 = __float_as_uint(qB[2 * ks + 1]);
                mma_tf32(S0, a0, a1, a2, a3,
                         __float_as_uint(Kb0[ks * 8]), __float_as_uint(Kb0[ks * 8 + 4]));
                mma_tf32(S1, a0, a1, a2, a3,
                         __float_as_uint(Kb1[ks * 8]), __float_as_uint(Kb1[ks * 8 + 4]));
            }

            // exp (base-2), rowsum partials, stage to smem
            float p00 = ex2f(S0[0]), p01 = ex2f(S0[1]), p02 = ex2f(S0[2]), p03 = ex2f(S0[3]);
            float p10 = ex2f(S1[0]), p11 = ex2f(S1[1]), p12 = ex2f(S1[2]), p13 = ex2f(S1[3]);
            sumA += (p00 + p01) + (p10 + p11);
            sumB += (p02 + p03) + (p12 + p13);
            int col = jg * 16 + 2 * tg;
            *(float2*)(sbA + col)     = make_float2(p00, p01);
            *(float2*)(sbA + col + 8) = make_float2(p10, p11);
            *(float2*)(sbB + col)     = make_float2(p02, p03);
            *(float2*)(sbB + col + 8) = make_float2(p12, p13);

            // pack exp'd S accumulators -> fp16 A-frag for PV
            unsigned pa0 = pack_h2(p00, p01);
            unsigned pa1 = pack_h2(p02, p03);
            unsigned pa2 = pack_h2(p10, p11);
            unsigned pa3 = pack_h2(p12, p13);

#pragma unroll
            for (int ng = 0; ng < 4; ng++) {
                unsigned b0, b1, b2, b3;
                ldsm_x4_t(b0, b1, b2, b3, vaddr + jg * (16 * VLD * 2) + ng * 32);
                mma_f16(cacc[2 * ng],     pa0, pa1, pa2, pa3, b0, b1);
                mma_f16(cacc[2 * ng + 1], pa0, pa1, pa2, pa3, b2, b3);
            }
        }

        __syncthreads();   // exp tile staged; coalesced store
#pragma unroll
        for (int j = 0; j < 8; j++) {
            float4 v = *(float4*)(Sb + sr * SLD + sc + 4 * j);
            *(float4*)(arow + (size_t)it * 64 + 4 * j) = v;
        }
    }

    // rowsum reduce within quad
    sumA += __shfl_xor_sync(0xffffffffu, sumA, 1);
    sumA += __shfl_xor_sync(0xffffffffu, sumA, 2);
    sumB += __shfl_xor_sync(0xffffffffu, sumB, 1);
    sumB += __shfl_xor_sync(0xffffffffu, sumB, 2);
    float invA = 1.0f / sumA, invB = 1.0f / sumB;
    if (tg == 0) {
        g_rowinv[bh * TT + t0 + warp * 16 + g] = invA;
        g_rowinv[bh * TT + t0 + warp * 16 + 8 + g] = invB;
    }

    // ctx: normalize, round to tf32 (gemm_out is convert-free), store
    float* cA = g_ctx + (size_t)(b * TT + t0 + warp * 16 + g) * EE + h * HD + 2 * tg;
    float* cB = cA + (size_t)8 * EE;
#pragma unroll
    for (int jn = 0; jn < 8; jn++) {
        *(float2*)(cA + 8 * jn) = make_float2(wmma::__float_to_tf32(cacc[jn][0] * invA),
                                              wmma::__float_to_tf32(cacc[jn][1] * invA));
        *(float2*)(cB + 8 * jn) = make_float2(wmma::__float_to_tf32(cacc[jn][2] * invB),
                                              wmma::__float_to_tf32(cacc[jn][3] * invB));
    }
}

// ---------------------------------------------------------------------------
// Streaming rescale: attn *= rowinv[row]. Pure bandwidth (1.07 GB).
// ---------------------------------------------------------------------------

__global__ __launch_bounds__(256)
void rescale_kernel(float* __restrict__ attn)
{
    const size_t n4 = (size_t)BB * NH * TT * SS / 4;
    size_t i = (size_t)blockIdx.x * blockDim.x + threadIdx.x;
    const size_t stride = (size_t)gridDim.x * blockDim.x;
    float4* a4 = (float4*)attn;
    for (; i < n4; i += stride) {
        float inv = __ldg(&g_rowinv[i >> 9]);
        float4 v = a4[i];
        v.x *= inv; v.y *= inv; v.z *= inv; v.w *= inv;
        a4[i] = v;
    }
}

// ---------------------------------------------------------------------------

extern "C" void kernel_launch(void* const* d_in, const int* in_sizes, int n_in,
                              void* d_out, int out_size)
{
    const float* src = (const float*)d_in[0];
    const float* tgt = (const float*)d_in[1];
    const float* Wq  = (const float*)d_in[2];
    const float* Wk  = (const float*)d_in[3];
    const float* Wv  = (const float*)d_in[4];
    const float* Wo  = (const float*)d_in[5];
    const float* bo  = (const float*)d_in[6];

    float* out  = (float*)d_out;                  // [2,2048,1024]
    float* attn = out + (size_t)MM * EE;          // [2,16,2048,2048]

    // resolve device-global addresses for round_kernel destinations
    float *p_src, *p_tgt, *p_wq, *p_wk, *p_wv, *p_wo;
    cudaGetSymbolAddress((void**)&p_src, r_src);
    cudaGetSymbolAddress((void**)&p_tgt, r_tgt);
    cudaGetSymbolAddress((void**)&p_wq,  r_wq);
    cudaGetSymbolAddress((void**)&p_wk,  r_wk);
    cudaGetSymbolAddress((void**)&p_wv,  r_wv);
    cudaGetSymbolAddress((void**)&p_wo,  r_wo);

    const int attn_smem = (2 * 64 * KLD + 64 * VLD + 128 * SLD) * 4;   // 88064 B
    cudaFuncSetAttribute(attn_kernel, cudaFuncAttributeMaxDynamicSharedMemorySize, attn_smem);

    // pre-round all GEMM inputs to tf32 (streaming, ~20 us total)
    round_kernel<<<1024, 256>>>((const float4*)src, (float4*)p_src, MM * EE / 4);
    round_kernel<<<1024, 256>>>((const float4*)tgt, (float4*)p_tgt, MM * EE / 4);
    round_kernel<<<512, 256>>>((const float4*)Wq, (float4*)p_wq, EE * EE / 4);
    round_kernel<<<512, 256>>>((const float4*)Wk, (float4*)p_wk, EE * EE / 4);
    round_kernel<<<512, 256>>>((const float4*)Wv, (float4*)p_wv, EE * EE / 4);
    round_kernel<<<512, 256>>>((const float4*)Wo, (float4*)p_wo, EE * EE / 4);

    dim3 g1(8, 32, 3);
    gemm_qkv_kernel<<<g1, 256>>>();

    dim3 g2(16, 32);
    attn_kernel<<<g2, 256, attn_smem>>>(attn);

    dim3 g3(8, 32);
    gemm_out_kernel<<<g3, 256>>>(bo, out);

    rescale_kernel<<<8192, 256>>>(attn);
}

// round 12
// speedup vs baseline: 1.1702x; 1.1702x over previous
#include <cuda_runtime.h>
#include <cuda_fp16.h>
#include <mma.h>
using namespace nvcuda;

#define NH 16
#define HD 64
#define BB 2
#define TT 2048
#define SS 2048
#define EE 1024
#define MM (BB * TT)   // 4096 rows

// Scratch (allocation-free: device globals). Layout [B*T, E] = [b,t,h,d].
__device__ float  g_q[MM * EE];
__device__ float  g_k[MM * EE];     // tf32-rounded by gemm epilogue
__device__ __half g_v[MM * EE];     // fp16, by gemm epilogue
__device__ float  g_ctx[MM * EE];   // tf32-rounded by attn epilogue
__device__ float  g_rowinv[BB * NH * TT];

// tf32 pre-rounded copies of GEMM inputs (kills all in-loop F2FP converts)
__device__ float  r_src[MM * EE];
__device__ float  r_tgt[MM * EE];
__device__ float  r_wq[EE * EE];
__device__ float  r_wk[EE * EE];
__device__ float  r_wv[EE * EE];
__device__ float  r_wo[EE * EE];

// ---------------- helpers ----------------
__device__ __forceinline__ void cpa16(void* s, const void* g) {
    unsigned sa = (unsigned)__cvta_generic_to_shared(s);
    asm volatile("cp.async.ca.shared.global [%0], [%1], 16;\n" :: "r"(sa), "l"(g));
}
__device__ __forceinline__ void cp_commit() {
    asm volatile("cp.async.commit_group;\n");
}
template<int N> __device__ __forceinline__ void cp_wait() {
    asm volatile("cp.async.wait_group %0;\n" :: "n"(N));
}
__device__ __forceinline__ float ex2f(float x) {
    float y;
    asm("ex2.approx.f32 %0, %1;" : "=f"(y) : "f"(x));
    return y;
}
__device__ __forceinline__ void mma_tf32(float* c, unsigned a0, unsigned a1,
                                         unsigned a2, unsigned a3,
                                         unsigned b0, unsigned b1) {
    asm volatile(
        "mma.sync.aligned.m16n8k8.row.col.f32.tf32.tf32.f32 "
        "{%0,%1,%2,%3},{%4,%5,%6,%7},{%8,%9},{%0,%1,%2,%3};"
        : "+f"(c[0]), "+f"(c[1]), "+f"(c[2]), "+f"(c[3])
        : "r"(a0), "r"(a1), "r"(a2), "r"(a3), "r"(b0), "r"(b1));
}
__device__ __forceinline__ void mma_f16(float* c, unsigned a0, unsigned a1,
                                        unsigned a2, unsigned a3,
                                        unsigned b0, unsigned b1) {
    asm volatile(
        "mma.sync.aligned.m16n8k16.row.col.f32.f16.f16.f32 "
        "{%0,%1,%2,%3},{%4,%5,%6,%7},{%8,%9},{%0,%1,%2,%3};"
        : "+f"(c[0]), "+f"(c[1]), "+f"(c[2]), "+f"(c[3])
        : "r"(a0), "r"(a1), "r"(a2), "r"(a3), "r"(b0), "r"(b1));
}
__device__ __forceinline__ void ldsm_x4_t(unsigned& r0, unsigned& r1,
                                          unsigned& r2, unsigned& r3, unsigned addr) {
    asm volatile("ldmatrix.sync.aligned.m8n8.x4.trans.shared.b16 {%0,%1,%2,%3},[%4];"
                 : "=r"(r0), "=r"(r1), "=r"(r2), "=r"(r3) : "r"(addr));
}
__device__ __forceinline__ unsigned pack_h2(float lo, float hi) {
    __half2 h = __floats2half2_rn(lo, hi);
    return *(unsigned*)&h;
}

// ---------------------------------------------------------------------------
// Pre-round: out = tf32_rn(in) for all 6 GEMM inputs in ONE launch.
// grid.y selects the array.
// ---------------------------------------------------------------------------
__global__ __launch_bounds__(256)
void round_all_kernel(const float4* __restrict__ src, const float4* __restrict__ tgt,
                      const float4* __restrict__ wq, const float4* __restrict__ wk,
                      const float4* __restrict__ wv, const float4* __restrict__ wo)
{
    const float4* in;
    float4* out;
    int n4;
    switch (blockIdx.y) {
        case 0: in = src; out = (float4*)r_src; n4 = MM * EE / 4; break;
        case 1: in = tgt; out = (float4*)r_tgt; n4 = MM * EE / 4; break;
        case 2: in = wq;  out = (float4*)r_wq;  n4 = EE * EE / 4; break;
        case 3: in = wk;  out = (float4*)r_wk;  n4 = EE * EE / 4; break;
        case 4: in = wv;  out = (float4*)r_wv;  n4 = EE * EE / 4; break;
        default: in = wo; out = (float4*)r_wo;  n4 = EE * EE / 4; break;
    }
    int i = blockIdx.x * blockDim.x + threadIdx.x;
    int stride = gridDim.x * blockDim.x;
    for (; i < n4; i += stride) {
        float4 v = in[i];
        v.x = wmma::__float_to_tf32(v.x);
        v.y = wmma::__float_to_tf32(v.y);
        v.z = wmma::__float_to_tf32(v.z);
        v.w = wmma::__float_to_tf32(v.w);
        out[i] = v;
    }
}

// ---------------------------------------------------------------------------
// NT GEMM (TF32 WMMA): C[M,N] = A[M,1024] * W[N,1024]^T
// Inputs are PRE-ROUNDED tf32 — no in-loop converts.
// BM=128, BN=128, BK=32, 256 threads, warp grid 4x2, warp tile 32x64.
// 2-stage cp.async double buffer.
// MODE: 0 = float raw (Q), 1 = float tf32-rounded (K), 2 = half (V),
//       3 = float + bias (output projection)
// ---------------------------------------------------------------------------

#define GLDA 36   // 32 + 4 pad

template<int MODE>
__device__ __forceinline__ void gemm_body(const float* __restrict__ A,
                                          const float* __restrict__ W,
                                          float* __restrict__ O,
                                          __half* __restrict__ Oh,
                                          const float* __restrict__ bo)
{
    __shared__ __align__(16) float smem_all[4 * 128 * GLDA];   // 73728 B
    float* As0 = smem_all;
    float* As1 = smem_all + 128 * GLDA;
    float* Ws0 = smem_all + 2 * 128 * GLDA;
    float* Ws1 = smem_all + 3 * 128 * GLDA;

    const int tid = threadIdx.x;
    const int warp = tid >> 5;
    const int wm = warp >> 1;
    const int wn = warp & 1;
    const int m0 = blockIdx.y * 128;
    const int n0 = blockIdx.x * 128;

    wmma::fragment<wmma::accumulator, 16, 16, 8, float> acc[2][4];
#pragma unroll
    for (int i = 0; i < 2; i++)
#pragma unroll
        for (int j = 0; j < 4; j++) wmma::fill_fragment(acc[i][j], 0.0f);

#pragma unroll
    for (int i = 0; i < 4; i++) {
        int e = tid + i * 256;
        int r = e >> 3, c = (e & 7) * 4;
        cpa16(As0 + r * GLDA + c, A + (size_t)(m0 + r) * 1024 + c);
        cpa16(Ws0 + r * GLDA + c, W + (size_t)(n0 + r) * 1024 + c);
    }
    cp_commit();

    for (int t = 0; t < 32; t++) {
        if (t < 31) {
            int k0 = (t + 1) * 32;
            float* ad = ((t + 1) & 1) ? As1 : As0;
            float* wd = ((t + 1) & 1) ? Ws1 : Ws0;
#pragma unroll
            for (int i = 0; i < 4; i++) {
                int e = tid + i * 256;
                int r = e >> 3, c = (e & 7) * 4;
                cpa16(ad + r * GLDA + c, A + (size_t)(m0 + r) * 1024 + k0 + c);
                cpa16(wd + r * GLDA + c, W + (size_t)(n0 + r) * 1024 + k0 + c);
            }
            cp_commit();
            cp_wait<1>();
        } else {
            cp_wait<0>();
        }
        __syncthreads();

        const float* as = (t & 1) ? As1 : As0;
        const float* ws = (t & 1) ? Ws1 : Ws0;
#pragma unroll
        for (int kk = 0; kk < 32; kk += 8) {
            wmma::fragment<wmma::matrix_a, 16, 16, 8, wmma::precision::tf32, wmma::row_major> af[2];
            wmma::fragment<wmma::matrix_b, 16, 16, 8, wmma::precision::tf32, wmma::col_major> bf[4];
#pragma unroll
            for (int i = 0; i < 2; i++)
                wmma::load_matrix_sync(af[i], as + (wm * 32 + i * 16) * GLDA + kk, GLDA);
#pragma unroll
            for (int j = 0; j < 4; j++)
                wmma::load_matrix_sync(bf[j], ws + (wn * 64 + j * 16) * GLDA + kk, GLDA);
#pragma unroll
            for (int i = 0; i < 2; i++)
#pragma unroll
                for (int j = 0; j < 4; j++)
                    wmma::mma_sync(acc[i][j], af[i], bf[j], acc[i][j]);
        }
        __syncthreads();
    }

    if (MODE == 3) {
        float* Cs = smem_all;      // 128 x 132
#pragma unroll
        for (int i = 0; i < 2; i++)
#pragma unroll
            for (int j = 0; j < 4; j++)
                wmma::store_matrix_sync(Cs + (wm * 32 + i * 16) * 132 + wn * 64 + j * 16,
                                        acc[i][j], 132, wmma::mem_row_major);
        __syncthreads();
#pragma unroll
        for (int i = 0; i < 16; i++) {
            int e = tid + i * 256;
            int r = e >> 5, c = (e & 31) * 4;
            float4 v = *(float4*)(Cs + r * 132 + c);
            float4 b4 = *(const float4*)(bo + n0 + c);
            v.x += b4.x; v.y += b4.y; v.z += b4.z; v.w += b4.w;
            *(float4*)(O + (size_t)(m0 + r) * EE + n0 + c) = v;
        }
    } else if (MODE == 2) {
        float* Cs = smem_all;
#pragma unroll
        for (int i = 0; i < 2; i++)
#pragma unroll
            for (int j = 0; j < 4; j++)
                wmma::store_matrix_sync(Cs + (wm * 32 + i * 16) * 132 + wn * 64 + j * 16,
                                        acc[i][j], 132, wmma::mem_row_major);
        __syncthreads();
#pragma unroll
        for (int i = 0; i < 16; i++) {
            int e = tid + i * 256;
            int r = e >> 5, c = (e & 31) * 4;
            float4 v = *(float4*)(Cs + r * 132 + c);
            __half2 h0 = __floats2half2_rn(v.x, v.y);
            __half2 h1 = __floats2half2_rn(v.z, v.w);
            unsigned u0 = *(unsigned*)&h0, u1 = *(unsigned*)&h1;
            uint2 pk = make_uint2(u0, u1);
            *(uint2*)(Oh + (size_t)(m0 + r) * EE + n0 + c) = pk;
        }
    } else {
        if (MODE == 1) {
#pragma unroll
            for (int i = 0; i < 2; i++)
#pragma unroll
                for (int j = 0; j < 4; j++)
#pragma unroll
                    for (int x = 0; x < acc[i][j].num_elements; x++)
                        acc[i][j].x[x] = wmma::__float_to_tf32(acc[i][j].x[x]);
        }
#pragma unroll
        for (int i = 0; i < 2; i++)
#pragma unroll
            for (int j = 0; j < 4; j++)
                wmma::store_matrix_sync(
                    O + (size_t)(m0 + wm * 32 + i * 16) * 1024 + n0 + wn * 64 + j * 16,
                    acc[i][j], 1024, wmma::mem_row_major);
    }
}

__global__ __launch_bounds__(256)
void gemm_qkv_kernel()
{
    const int z = blockIdx.z;
    if (z == 0)      gemm_body<0>(r_tgt, r_wq, g_q, nullptr, nullptr);
    else if (z == 1) gemm_body<1>(r_src, r_wk, g_k, nullptr, nullptr);
    else             gemm_body<2>(r_src, r_wv, nullptr, g_v, nullptr);
}

__global__ __launch_bounds__(256)
void gemm_out_kernel(const float* __restrict__ bo, float* __restrict__ out)
{
    gemm_body<3>(g_ctx, r_wo, out, nullptr, bo);
}

// ---------------------------------------------------------------------------
// Attention, register-resident P, single pass over keys.
// Each warp owns 16 query rows. Per 64-key tile:
//   QK via mma.m16n8k8.tf32; exp in regs (base-2); STS exp tile to smem
//   (SLD=72 -> conflict-free); PV via mma.m16n8k16.f16; then coalesced
//   STG.128: 16 lanes per row -> 2 rows/warp-instr -> 4 lines (ideal).
// Rowsum in regs -> g_rowinv; rescale_kernel normalizes attn afterwards.
// ---------------------------------------------------------------------------

#define KLD 68   // K tile row stride (floats)
#define VLD 72   // V tile row stride (halves)
#define SLD 72   // staged attn tile row stride (floats) — conflict-free STS/LDS

__global__ __launch_bounds__(256, 2)
void attn_kernel(float* __restrict__ attn_out)
{
    extern __shared__ __align__(16) float sm[];
    float*  K0 = sm;                            // 64*KLD floats
    float*  K1 = sm + 64 * KLD;
    __half* V0 = (__half*)(sm + 2 * 64 * KLD);  // 64*VLD halves
    __half* V1 = V0 + 64 * VLD;
    float*  Sb = sm + 2 * 64 * KLD + 64 * VLD;  // 128*SLD floats (staging)

    const int tid = threadIdx.x;
    const int warp = tid >> 5, lane = tid & 31;
    const int g = lane >> 2, tg = lane & 3;
    const int bh = blockIdx.y, b = bh >> 4, h = bh & 15;
    const int t0 = blockIdx.x * 128;

    const float*  kbase = g_k + (size_t)(b * SS) * EE + h * HD;
    const __half* vbase = g_v + (size_t)(b * SS) * EE + h * HD;

    // prologue: tile 0 loads in flight while Q loads run
#pragma unroll
    for (int i = 0; i < 4; i++) {
        int e = tid + i * 256, r = e >> 4, c = (e & 15) * 4;
        cpa16(K0 + r * KLD + c, kbase + (size_t)r * EE + c);
    }
#pragma unroll
    for (int i = 0; i < 2; i++) {
        int e = tid + i * 256, r = e >> 3, c = (e & 7) * 8;
        cpa16(V0 + r * VLD + c, vbase + (size_t)r * EE + c);
    }
    cp_commit();

    // Q into registers: rows (t0+16w+g) and (+8), cols tg+4i; scaled to base-2
    const float QSC = 1.44269504f * 0.125f;
    float qA[16], qB[16];
    {
        const float* qp = g_q + (size_t)(b * TT + t0 + warp * 16 + g) * EE + h * HD + tg;
#pragma unroll
        for (int i = 0; i < 16; i++) {
            qA[i] = wmma::__float_to_tf32(qp[4 * i] * QSC);
            qB[i] = wmma::__float_to_tf32(qp[(size_t)8 * EE + 4 * i] * QSC);
        }
    }

    float cacc[8][4];
#pragma unroll
    for (int j = 0; j < 8; j++)
#pragma unroll
        for (int x = 0; x < 4; x++) cacc[j][x] = 0.0f;
    float sumA = 0.0f, sumB = 0.0f;

    // STS coords for the exp tile
    float* sbA = Sb + (warp * 16 + g) * SLD;    // row (16w+g)
    float* sbB = sbA + 8 * SLD;                 // row (+8)

    for (int it = 0; it < 32; it++) {
        cp_wait<0>();
        __syncthreads();

        // prefetch tile it+1 into the other buffer
        if (it + 1 < 32) {
            float*  Kd = (it & 1) ? K0 : K1;
            __half* Vd = (it & 1) ? V0 : V1;
            const float*  ksrc = kbase + (size_t)(it + 1) * 64 * EE;
            const __half* vsrc = vbase + (size_t)(it + 1) * 64 * EE;
#pragma unroll
            for (int i = 0; i < 4; i++) {
                int e = tid + i * 256, r = e >> 4, c = (e & 15) * 4;
                cpa16(Kd + r * KLD + c, ksrc + (size_t)r * EE + c);
            }
#pragma unroll
            for (int i = 0; i < 2; i++) {
                int e = tid + i * 256, r = e >> 3, c = (e & 7) * 8;
                cpa16(Vd + r * VLD + c, vsrc + (size_t)r * EE + c);
            }
            cp_commit();
        }

        const float*  K = (it & 1) ? K1 : K0;
        const __half* V = (it & 1) ? V1 : V0;
        unsigned vaddr = (unsigned)__cvta_generic_to_shared(
            V + (lane & 15) * VLD + (lane >> 4) * 8);

#pragma unroll
        for (int jg = 0; jg < 4; jg++) {
            float S0[4] = {0, 0, 0, 0}, S1[4] = {0, 0, 0, 0};
            const float* Kb0 = K + (jg * 16 + g) * KLD + tg;
            const float* Kb1 = K + (jg * 16 + 8 + g) * KLD + tg;
#pragma unroll
            for (int ks = 0; ks < 8; ks++) {
                unsigned a0 = __float_as_uint(qA[2 * ks]);
                unsigned a1 = __float_as_uint(qB[2 * ks]);
                unsigned a2 = __float_as_uint(qA[2 * ks + 1]);
                unsigned a3 = __float_as_uint(qB[2 * ks + 1]);
                mma_tf32(S0, a0, a1, a2, a3,
                         __float_as_uint(Kb0[ks * 8]), __float_as_uint(Kb0[ks * 8 + 4]));
                mma_tf32(S1, a0, a1, a2, a3,
                         __float_as_uint(Kb1[ks * 8]), __float_as_uint(Kb1[ks * 8 + 4]));
            }

            // exp (base-2), rowsum partials, stage to smem
            float p00 = ex2f(S0[0]), p01 = ex2f(S0[1]), p02 = ex2f(S0[2]), p03 = ex2f(S0[3]);
            float p10 = ex2f(S1[0]), p11 = ex2f(S1[1]), p12 = ex2f(S1[2]), p13 = ex2f(S1[3]);
            sumA += (p00 + p01) + (p10 + p11);
            sumB += (p02 + p03) + (p12 + p13);
            int col = jg * 16 + 2 * tg;
            *(float2*)(sbA + col)     = make_float2(p00, p01);
            *(float2*)(sbA + col + 8) = make_float2(p10, p11);
            *(float2*)(sbB + col)     = make_float2(p02, p03);
            *(float2*)(sbB + col + 8) = make_float2(p12, p13);

            // pack exp'd S accumulators -> fp16 A-frag for PV
            unsigned pa0 = pack_h2(p00, p01);
            unsigned pa1 = pack_h2(p02, p03);
            unsigned pa2 = pack_h2(p10, p11);
            unsigned pa3 = pack_h2(p12, p13);

#pragma unroll
            for (int ng = 0; ng < 4; ng++) {
                unsigned b0, b1, b2, b3;
                ldsm_x4_t(b0, b1, b2, b3, vaddr + jg * (16 * VLD * 2) + ng * 32);
                mma_f16(cacc[2 * ng],     pa0, pa1, pa2, pa3, b0, b1);
                mma_f16(cacc[2 * ng + 1], pa0, pa1, pa2, pa3, b2, b3);
            }
        }

        __syncthreads();   // exp tile fully staged
        // coalesced STG: 16 lanes per row -> 2 rows per warp-instr -> 4 lines
#pragma unroll
        for (int j = 0; j < 8; j++) {
            int e = tid + j * 256;
            int r = e >> 4, c = (e & 15) * 4;
            float4 v = *(float4*)(Sb + r * SLD + c);
            *(float4*)(attn_out + (size_t)(bh * TT + t0 + r) * SS + it * 64 + c) = v;
        }
    }

    // rowsum reduce within quad
    sumA += __shfl_xor_sync(0xffffffffu, sumA, 1);
    sumA += __shfl_xor_sync(0xffffffffu, sumA, 2);
    sumB += __shfl_xor_sync(0xffffffffu, sumB, 1);
    sumB += __shfl_xor_sync(0xffffffffu, sumB, 2);
    float invA = 1.0f / sumA, invB = 1.0f / sumB;
    if (tg == 0) {
        g_rowinv[bh * TT + t0 + warp * 16 + g] = invA;
        g_rowinv[bh * TT + t0 + warp * 16 + 8 + g] = invB;
    }

    // ctx: normalize, round to tf32 (gemm_out is convert-free), store
    float* cA = g_ctx + (size_t)(b * TT + t0 + warp * 16 + g) * EE + h * HD + 2 * tg;
    float* cB = cA + (size_t)8 * EE;
#pragma unroll
    for (int jn = 0; jn < 8; jn++) {
        *(float2*)(cA + 8 * jn) = make_float2(wmma::__float_to_tf32(cacc[jn][0] * invA),
                                              wmma::__float_to_tf32(cacc[jn][1] * invA));
        *(float2*)(cB + 8 * jn) = make_float2(wmma::__float_to_tf32(cacc[jn][2] * invB),
                                              wmma::__float_to_tf32(cacc[jn][3] * invB));
    }
}

// ---------------------------------------------------------------------------
// Streaming rescale: attn *= rowinv[row]. Pure bandwidth (1.07 GB).
// ---------------------------------------------------------------------------

__global__ __launch_bounds__(256)
void rescale_kernel(float* __restrict__ attn)
{
    const size_t n4 = (size_t)BB * NH * TT * SS / 4;
    size_t i = (size_t)blockIdx.x * blockDim.x + threadIdx.x;
    const size_t stride = (size_t)gridDim.x * blockDim.x;
    float4* a4 = (float4*)attn;
    for (; i < n4; i += stride) {
        float inv = __ldg(&g_rowinv[i >> 9]);
        float4 v = a4[i];
        v.x *= inv; v.y *= inv; v.z *= inv; v.w *= inv;
        a4[i] = v;
    }
}

// ---------------------------------------------------------------------------

extern "C" void kernel_launch(void* const* d_in, const int* in_sizes, int n_in,
                              void* d_out, int out_size)
{
    const float* src = (const float*)d_in[0];
    const float* tgt = (const float*)d_in[1];
    const float* Wq  = (const float*)d_in[2];
    const float* Wk  = (const float*)d_in[3];
    const float* Wv  = (const float*)d_in[4];
    const float* Wo  = (const float*)d_in[5];
    const float* bo  = (const float*)d_in[6];

    float* out  = (float*)d_out;                  // [2,2048,1024]
    float* attn = out + (size_t)MM * EE;          // [2,16,2048,2048]

    const int attn_smem = (2 * 64 * KLD + 64 * VLD + 128 * SLD) * 4;   // 90112 B
    cudaFuncSetAttribute(attn_kernel, cudaFuncAttributeMaxDynamicSharedMemorySize, attn_smem);

    // pre-round all GEMM inputs to tf32, one launch
    dim3 gr(512, 6);
    round_all_kernel<<<gr, 256>>>((const float4*)src, (const float4*)tgt,
                                  (const float4*)Wq, (const float4*)Wk,
                                  (const float4*)Wv, (const float4*)Wo);

    dim3 g1(8, 32, 3);
    gemm_qkv_kernel<<<g1, 256>>>();

    dim3 g2(16, 32);
    attn_kernel<<<g2, 256, attn_smem>>>(attn);

    dim3 g3(8, 32);
    gemm_out_kernel<<<g3, 256>>>(bo, out);

    rescale_kernel<<<8192, 256>>>(attn);
}

// round 13
// speedup vs baseline: 1.2824x; 1.0959x over previous
#include <cuda_runtime.h>
#include <cuda_fp16.h>
#include <mma.h>
using namespace nvcuda;

#define NH 16
#define HD 64
#define BB 2
#define TT 2048
#define SS 2048
#define EE 1024
#define MM (BB * TT)   // 4096 rows

// Scratch (allocation-free: device globals). Layout [B*T, E] = [b,t,h,d].
__device__ float  g_q[MM * EE];
__device__ __half g_k[MM * EE];     // fp16, by gemm epilogue
__device__ __half g_v[MM * EE];     // fp16, by gemm epilogue
__device__ float  g_ctx[MM * EE];   // tf32-rounded by attn epilogue
__device__ float  g_rowinv[BB * NH * TT];

// tf32 pre-rounded copies of GEMM inputs (kills all in-loop F2FP converts)
__device__ float  r_src[MM * EE];
__device__ float  r_tgt[MM * EE];
__device__ float  r_wq[EE * EE];
__device__ float  r_wk[EE * EE];
__device__ float  r_wv[EE * EE];
__device__ float  r_wo[EE * EE];

// ---------------- helpers ----------------
__device__ __forceinline__ void cpa16(void* s, const void* g) {
    unsigned sa = (unsigned)__cvta_generic_to_shared(s);
    asm volatile("cp.async.ca.shared.global [%0], [%1], 16;\n" :: "r"(sa), "l"(g));
}
__device__ __forceinline__ void cp_commit() {
    asm volatile("cp.async.commit_group;\n");
}
template<int N> __device__ __forceinline__ void cp_wait() {
    asm volatile("cp.async.wait_group %0;\n" :: "n"(N));
}
__device__ __forceinline__ float ex2f(float x) {
    float y;
    asm("ex2.approx.f32 %0, %1;" : "=f"(y) : "f"(x));
    return y;
}
__device__ __forceinline__ void mma_f16(float* c, unsigned a0, unsigned a1,
                                        unsigned a2, unsigned a3,
                                        unsigned b0, unsigned b1) {
    asm volatile(
        "mma.sync.aligned.m16n8k16.row.col.f32.f16.f16.f32 "
        "{%0,%1,%2,%3},{%4,%5,%6,%7},{%8,%9},{%0,%1,%2,%3};"
        : "+f"(c[0]), "+f"(c[1]), "+f"(c[2]), "+f"(c[3])
        : "r"(a0), "r"(a1), "r"(a2), "r"(a3), "r"(b0), "r"(b1));
}
__device__ __forceinline__ void ldsm_x4(unsigned& r0, unsigned& r1,
                                        unsigned& r2, unsigned& r3, unsigned addr) {
    asm volatile("ldmatrix.sync.aligned.m8n8.x4.shared.b16 {%0,%1,%2,%3},[%4];"
                 : "=r"(r0), "=r"(r1), "=r"(r2), "=r"(r3) : "r"(addr));
}
__device__ __forceinline__ void ldsm_x4_t(unsigned& r0, unsigned& r1,
                                          unsigned& r2, unsigned& r3, unsigned addr) {
    asm volatile("ldmatrix.sync.aligned.m8n8.x4.trans.shared.b16 {%0,%1,%2,%3},[%4];"
                 : "=r"(r0), "=r"(r1), "=r"(r2), "=r"(r3) : "r"(addr));
}
__device__ __forceinline__ unsigned pack_h2(float lo, float hi) {
    __half2 h = __floats2half2_rn(lo, hi);
    return *(unsigned*)&h;
}

// ---------------------------------------------------------------------------
// Pre-round: out = tf32_rn(in) for all 6 GEMM inputs in ONE launch.
// ---------------------------------------------------------------------------
__global__ __launch_bounds__(256)
void round_all_kernel(const float4* __restrict__ src, const float4* __restrict__ tgt,
                      const float4* __restrict__ wq, const float4* __restrict__ wk,
                      const float4* __restrict__ wv, const float4* __restrict__ wo)
{
    const float4* in;
    float4* out;
    int n4;
    switch (blockIdx.y) {
        case 0: in = src; out = (float4*)r_src; n4 = MM * EE / 4; break;
        case 1: in = tgt; out = (float4*)r_tgt; n4 = MM * EE / 4; break;
        case 2: in = wq;  out = (float4*)r_wq;  n4 = EE * EE / 4; break;
        case 3: in = wk;  out = (float4*)r_wk;  n4 = EE * EE / 4; break;
        case 4: in = wv;  out = (float4*)r_wv;  n4 = EE * EE / 4; break;
        default: in = wo; out = (float4*)r_wo;  n4 = EE * EE / 4; break;
    }
    int i = blockIdx.x * blockDim.x + threadIdx.x;
    int stride = gridDim.x * blockDim.x;
    for (; i < n4; i += stride) {
        float4 v = in[i];
        v.x = wmma::__float_to_tf32(v.x);
        v.y = wmma::__float_to_tf32(v.y);
        v.z = wmma::__float_to_tf32(v.z);
        v.w = wmma::__float_to_tf32(v.w);
        out[i] = v;
    }
}

// ---------------------------------------------------------------------------
// NT GEMM (TF32 WMMA): C[M,N] = A[M,1024] * W[N,1024]^T
// Inputs PRE-ROUNDED tf32. BM=128, BN=128, BK=32, 256 threads, 4x2 warps,
// warp tile 32x64, 2-stage cp.async. __launch_bounds__(256,2) -> 2 CTAs/SM.
// MODE: 0 = float raw (Q), 2 = half (K/V), 3 = float + bias (out proj)
// ---------------------------------------------------------------------------

#define GLDA 36   // 32 + 4 pad

template<int MODE>
__device__ __forceinline__ void gemm_body(const float* __restrict__ A,
                                          const float* __restrict__ W,
                                          float* __restrict__ O,
                                          __half* __restrict__ Oh,
                                          const float* __restrict__ bo)
{
    __shared__ __align__(16) float smem_all[4 * 128 * GLDA];   // 73728 B
    float* As0 = smem_all;
    float* As1 = smem_all + 128 * GLDA;
    float* Ws0 = smem_all + 2 * 128 * GLDA;
    float* Ws1 = smem_all + 3 * 128 * GLDA;

    const int tid = threadIdx.x;
    const int warp = tid >> 5;
    const int wm = warp >> 1;
    const int wn = warp & 1;
    const int m0 = blockIdx.y * 128;
    const int n0 = blockIdx.x * 128;

    wmma::fragment<wmma::accumulator, 16, 16, 8, float> acc[2][4];
#pragma unroll
    for (int i = 0; i < 2; i++)
#pragma unroll
        for (int j = 0; j < 4; j++) wmma::fill_fragment(acc[i][j], 0.0f);

#pragma unroll
    for (int i = 0; i < 4; i++) {
        int e = tid + i * 256;
        int r = e >> 3, c = (e & 7) * 4;
        cpa16(As0 + r * GLDA + c, A + (size_t)(m0 + r) * 1024 + c);
        cpa16(Ws0 + r * GLDA + c, W + (size_t)(n0 + r) * 1024 + c);
    }
    cp_commit();

    for (int t = 0; t < 32; t++) {
        if (t < 31) {
            int k0 = (t + 1) * 32;
            float* ad = ((t + 1) & 1) ? As1 : As0;
            float* wd = ((t + 1) & 1) ? Ws1 : Ws0;
#pragma unroll
            for (int i = 0; i < 4; i++) {
                int e = tid + i * 256;
                int r = e >> 3, c = (e & 7) * 4;
                cpa16(ad + r * GLDA + c, A + (size_t)(m0 + r) * 1024 + k0 + c);
                cpa16(wd + r * GLDA + c, W + (size_t)(n0 + r) * 1024 + k0 + c);
            }
            cp_commit();
            cp_wait<1>();
        } else {
            cp_wait<0>();
        }
        __syncthreads();

        const float* as = (t & 1) ? As1 : As0;
        const float* ws = (t & 1) ? Ws1 : Ws0;
#pragma unroll
        for (int kk = 0; kk < 32; kk += 8) {
            wmma::fragment<wmma::matrix_a, 16, 16, 8, wmma::precision::tf32, wmma::row_major> af[2];
            wmma::fragment<wmma::matrix_b, 16, 16, 8, wmma::precision::tf32, wmma::col_major> bf[4];
#pragma unroll
            for (int i = 0; i < 2; i++)
                wmma::load_matrix_sync(af[i], as + (wm * 32 + i * 16) * GLDA + kk, GLDA);
#pragma unroll
            for (int j = 0; j < 4; j++)
                wmma::load_matrix_sync(bf[j], ws + (wn * 64 + j * 16) * GLDA + kk, GLDA);
#pragma unroll
            for (int i = 0; i < 2; i++)
#pragma unroll
                for (int j = 0; j < 4; j++)
                    wmma::mma_sync(acc[i][j], af[i], bf[j], acc[i][j]);
        }
        __syncthreads();
    }

    if (MODE == 3) {
        float* Cs = smem_all;      // 128 x 132
#pragma unroll
        for (int i = 0; i < 2; i++)
#pragma unroll
            for (int j = 0; j < 4; j++)
                wmma::store_matrix_sync(Cs + (wm * 32 + i * 16) * 132 + wn * 64 + j * 16,
                                        acc[i][j], 132, wmma::mem_row_major);
        __syncthreads();
#pragma unroll
        for (int i = 0; i < 16; i++) {
            int e = tid + i * 256;
            int r = e >> 5, c = (e & 31) * 4;
            float4 v = *(float4*)(Cs + r * 132 + c);
            float4 b4 = *(const float4*)(bo + n0 + c);
            v.x += b4.x; v.y += b4.y; v.z += b4.z; v.w += b4.w;
            *(float4*)(O + (size_t)(m0 + r) * EE + n0 + c) = v;
        }
    } else if (MODE == 2) {
        float* Cs = smem_all;
#pragma unroll
        for (int i = 0; i < 2; i++)
#pragma unroll
            for (int j = 0; j < 4; j++)
                wmma::store_matrix_sync(Cs + (wm * 32 + i * 16) * 132 + wn * 64 + j * 16,
                                        acc[i][j], 132, wmma::mem_row_major);
        __syncthreads();
#pragma unroll
        for (int i = 0; i < 16; i++) {
            int e = tid + i * 256;
            int r = e >> 5, c = (e & 31) * 4;
            float4 v = *(float4*)(Cs + r * 132 + c);
            __half2 h0 = __floats2half2_rn(v.x, v.y);
            __half2 h1 = __floats2half2_rn(v.z, v.w);
            unsigned u0 = *(unsigned*)&h0, u1 = *(unsigned*)&h1;
            uint2 pk = make_uint2(u0, u1);
            *(uint2*)(Oh + (size_t)(m0 + r) * EE + n0 + c) = pk;
        }
    } else {
#pragma unroll
        for (int i = 0; i < 2; i++)
#pragma unroll
            for (int j = 0; j < 4; j++)
                wmma::store_matrix_sync(
                    O + (size_t)(m0 + wm * 32 + i * 16) * 1024 + n0 + wn * 64 + j * 16,
                    acc[i][j], 1024, wmma::mem_row_major);
    }
}

__global__ __launch_bounds__(256, 2)
void gemm_qkv_kernel()
{
    const int z = blockIdx.z;
    if (z == 0)      gemm_body<0>(r_tgt, r_wq, g_q, nullptr, nullptr);
    else if (z == 1) gemm_body<2>(r_src, r_wk, nullptr, g_k, nullptr);
    else             gemm_body<2>(r_src, r_wv, nullptr, g_v, nullptr);
}

__global__ __launch_bounds__(256, 2)
void gemm_out_kernel(const float* __restrict__ bo, float* __restrict__ out)
{
    gemm_body<3>(g_ctx, r_wo, out, nullptr, bo);
}

// ---------------------------------------------------------------------------
// Attention, all-fp16 MMA, register-resident P, single pass over keys.
// Each warp owns 16 query rows. Per 64-key tile:
//   QK via mma.m16n8k16.f16 (Q packed fp16 in regs; K B-frags via ldmatrix.x4)
//   exp in regs (base-2; Q pre-scaled by log2e/8) -> STS staged tile
//   PV via mma.m16n8k16.f16 (P packed from accumulators, V via ldmatrix.trans)
//   coalesced STG.128 of staged tile (4 lines/warp-instr).
// fp16 has the same 11-bit significand as tf32 -> same error class.
// ---------------------------------------------------------------------------

#define KLD2 72  // K tile row stride (halves)
#define VLD 72   // V tile row stride (halves)
#define SLD 72   // staged attn tile row stride (floats)

__global__ __launch_bounds__(256, 2)
void attn_kernel(float* __restrict__ attn_out)
{
    extern __shared__ __align__(16) float sm[];
    __half* K0 = (__half*)sm;                   // 64*KLD2 halves (9216 B)
    __half* K1 = K0 + 64 * KLD2;
    __half* V0 = K1 + 64 * KLD2;                // 64*VLD halves
    __half* V1 = V0 + 64 * VLD;
    float*  Sb = (float*)(V1 + 64 * VLD);       // 128*SLD floats (staging)

    const int tid = threadIdx.x;
    const int warp = tid >> 5, lane = tid & 31;
    const int g = lane >> 2, tg = lane & 3;
    const int bh = blockIdx.y, b = bh >> 4, h = bh & 15;
    const int t0 = blockIdx.x * 128;

    const __half* kbase = g_k + (size_t)(b * SS) * EE + h * HD;
    const __half* vbase = g_v + (size_t)(b * SS) * EE + h * HD;

    // prologue: tile 0 (K+V fp16: 64 rows x 128B each)
#pragma unroll
    for (int i = 0; i < 2; i++) {
        int e = tid + i * 256, r = e >> 3, c = (e & 7) * 8;
        cpa16(K0 + r * KLD2 + c, kbase + (size_t)r * EE + c);
        cpa16(V0 + r * VLD + c, vbase + (size_t)r * EE + c);
    }
    cp_commit();

    // Q into fp16 regs: rows (t0+16w+g),(+8); a-frags per 16-hd k-block
    const float QSC = 1.44269504f * 0.125f;
    unsigned qh[4][4];
    {
        const float* qpA = g_q + (size_t)(b * TT + t0 + warp * 16 + g) * EE + h * HD;
        const float* qpB = qpA + (size_t)8 * EE;
#pragma unroll
        for (int kb = 0; kb < 4; kb++) {
            int c = kb * 16 + 2 * tg;
            qh[kb][0] = pack_h2(qpA[c] * QSC,     qpA[c + 1] * QSC);
            qh[kb][1] = pack_h2(qpB[c] * QSC,     qpB[c + 1] * QSC);
            qh[kb][2] = pack_h2(qpA[c + 8] * QSC, qpA[c + 9] * QSC);
            qh[kb][3] = pack_h2(qpB[c + 8] * QSC, qpB[c + 9] * QSC);
        }
    }

    float cacc[8][4];
#pragma unroll
    for (int j = 0; j < 8; j++)
#pragma unroll
        for (int x = 0; x < 4; x++) cacc[j][x] = 0.0f;
    float sumA = 0.0f, sumB = 0.0f;

    // STS coords for the exp tile
    float* sbA = Sb + (warp * 16 + g) * SLD;
    float* sbB = sbA + 8 * SLD;

    // per-lane ldmatrix address offsets for K (non-trans x4):
    // lanes 0-7: keys jg16+0..7 hd c0 | 8-15: same keys hd c0+8
    // lanes 16-23: keys +8 hd c0     | 24-31: keys +8 hd c0+8
    const int k_keyoff = ((lane >> 4) << 3) + (lane & 7);
    const int k_hdoff = (lane & 8) ? 16 : 0;   // bytes

    for (int it = 0; it < 32; it++) {
        cp_wait<0>();
        __syncthreads();

        // prefetch tile it+1
        if (it + 1 < 32) {
            __half* Kd = (it & 1) ? K0 : K1;
            __half* Vd = (it & 1) ? V0 : V1;
            const __half* ksrc = kbase + (size_t)(it + 1) * 64 * EE;
            const __half* vsrc = vbase + (size_t)(it + 1) * 64 * EE;
#pragma unroll
            for (int i = 0; i < 2; i++) {
                int e = tid + i * 256, r = e >> 3, c = (e & 7) * 8;
                cpa16(Kd + r * KLD2 + c, ksrc + (size_t)r * EE + c);
                cpa16(Vd + r * VLD + c, vsrc + (size_t)r * EE + c);
            }
            cp_commit();
        }

        const __half* K = (it & 1) ? K1 : K0;
        const __half* V = (it & 1) ? V1 : V0;
        unsigned kaddr = (unsigned)__cvta_generic_to_shared(K)
                       + k_keyoff * (KLD2 * 2) + k_hdoff;
        unsigned vaddr = (unsigned)__cvta_generic_to_shared(
            V + (lane & 15) * VLD + (lane >> 4) * 8);

#pragma unroll
        for (int jg = 0; jg < 4; jg++) {
            float S0[4] = {0, 0, 0, 0}, S1[4] = {0, 0, 0, 0};
#pragma unroll
            for (int kb = 0; kb < 4; kb++) {
                unsigned b0, b1, b2, b3;
                ldsm_x4(b0, b1, b2, b3, kaddr + jg * (16 * KLD2 * 2) + kb * 32);
                mma_f16(S0, qh[kb][0], qh[kb][1], qh[kb][2], qh[kb][3], b0, b1);
                mma_f16(S1, qh[kb][0], qh[kb][1], qh[kb][2], qh[kb][3], b2, b3);
            }

            // exp (base-2), rowsum partials, stage to smem
            float p00 = ex2f(S0[0]), p01 = ex2f(S0[1]), p02 = ex2f(S0[2]), p03 = ex2f(S0[3]);
            float p10 = ex2f(S1[0]), p11 = ex2f(S1[1]), p12 = ex2f(S1[2]), p13 = ex2f(S1[3]);
            sumA += (p00 + p01) + (p10 + p11);
            sumB += (p02 + p03) + (p12 + p13);
            int col = jg * 16 + 2 * tg;
            *(float2*)(sbA + col)     = make_float2(p00, p01);
            *(float2*)(sbA + col + 8) = make_float2(p10, p11);
            *(float2*)(sbB + col)     = make_float2(p02, p03);
            *(float2*)(sbB + col + 8) = make_float2(p12, p13);

            // pack exp'd S accumulators -> fp16 A-frag for PV
            unsigned pa0 = pack_h2(p00, p01);
            unsigned pa1 = pack_h2(p02, p03);
            unsigned pa2 = pack_h2(p10, p11);
            unsigned pa3 = pack_h2(p12, p13);

#pragma unroll
            for (int ng = 0; ng < 4; ng++) {
                unsigned b0, b1, b2, b3;
                ldsm_x4_t(b0, b1, b2, b3, vaddr + jg * (16 * VLD * 2) + ng * 32);
                mma_f16(cacc[2 * ng],     pa0, pa1, pa2, pa3, b0, b1);
                mma_f16(cacc[2 * ng + 1], pa0, pa1, pa2, pa3, b2, b3);
            }
        }

        __syncthreads();   // exp tile fully staged
        // coalesced STG: 16 lanes per row -> 2 rows per warp-instr -> 4 lines
#pragma unroll
        for (int j = 0; j < 8; j++) {
            int e = tid + j * 256;
            int r = e >> 4, c = (e & 15) * 4;
            float4 v = *(float4*)(Sb + r * SLD + c);
            *(float4*)(attn_out + (size_t)(bh * TT + t0 + r) * SS + it * 64 + c) = v;
        }
    }

    // rowsum reduce within quad
    sumA += __shfl_xor_sync(0xffffffffu, sumA, 1);
    sumA += __shfl_xor_sync(0xffffffffu, sumA, 2);
    sumB += __shfl_xor_sync(0xffffffffu, sumB, 1);
    sumB += __shfl_xor_sync(0xffffffffu, sumB, 2);
    float invA = 1.0f / sumA, invB = 1.0f / sumB;
    if (tg == 0) {
        g_rowinv[bh * TT + t0 + warp * 16 + g] = invA;
        g_rowinv[bh * TT + t0 + warp * 16 + 8 + g] = invB;
    }

    // ctx: normalize, round to tf32 (gemm_out is convert-free), store
    float* cA = g_ctx + (size_t)(b * TT + t0 + warp * 16 + g) * EE + h * HD + 2 * tg;
    float* cB = cA + (size_t)8 * EE;
#pragma unroll
    for (int jn = 0; jn < 8; jn++) {
        *(float2*)(cA + 8 * jn) = make_float2(wmma::__float_to_tf32(cacc[jn][0] * invA),
                                              wmma::__float_to_tf32(cacc[jn][1] * invA));
        *(float2*)(cB + 8 * jn) = make_float2(wmma::__float_to_tf32(cacc[jn][2] * invB),
                                              wmma::__float_to_tf32(cacc[jn][3] * invB));
    }
}

// ---------------------------------------------------------------------------
// Streaming rescale: attn *= rowinv[row]. Pure bandwidth (1.07 GB).
// ---------------------------------------------------------------------------

__global__ __launch_bounds__(256)
void rescale_kernel(float* __restrict__ attn)
{
    const size_t n4 = (size_t)BB * NH * TT * SS / 4;
    size_t i = (size_t)blockIdx.x * blockDim.x + threadIdx.x;
    const size_t stride = (size_t)gridDim.x * blockDim.x;
    float4* a4 = (float4*)attn;
    for (; i < n4; i += stride) {
        float inv = __ldg(&g_rowinv[i >> 9]);
        float4 v = a4[i];
        v.x *= inv; v.y *= inv; v.z *= inv; v.w *= inv;
        a4[i] = v;
    }
}

// ---------------------------------------------------------------------------

extern "C" void kernel_launch(void* const* d_in, const int* in_sizes, int n_in,
                              void* d_out, int out_size)
{
    const float* src = (const float*)d_in[0];
    const float* tgt = (const float*)d_in[1];
    const float* Wq  = (const float*)d_in[2];
    const float* Wk  = (const float*)d_in[3];
    const float* Wv  = (const float*)d_in[4];
    const float* Wo  = (const float*)d_in[5];
    const float* bo  = (const float*)d_in[6];

    float* out  = (float*)d_out;                  // [2,2048,1024]
    float* attn = out + (size_t)MM * EE;          // [2,16,2048,2048]

    const int attn_smem = (2 * 64 * KLD2 + 2 * 64 * VLD) * 2 + 128 * SLD * 4;  // 73728 B
    cudaFuncSetAttribute(attn_kernel, cudaFuncAttributeMaxDynamicSharedMemorySize, attn_smem);

    // pre-round all GEMM inputs to tf32, one launch
    dim3 gr(512, 6);
    round_all_kernel<<<gr, 256>>>((const float4*)src, (const float4*)tgt,
                                  (const float4*)Wq, (const float4*)Wk,
                                  (const float4*)Wv, (const float4*)Wo);

    dim3 g1(8, 32, 3);
    gemm_qkv_kernel<<<g1, 256>>>();

    dim3 g2(16, 32);
    attn_kernel<<<g2, 256, attn_smem>>>(attn);

    dim3 g3(8, 32);
    gemm_out_kernel<<<g3, 256>>>(bo, out);

    rescale_kernel<<<8192, 256>>>(attn);
}

// round 15
// speedup vs baseline: 2.3286x; 1.8158x over previous
#include <cuda_runtime.h>
#include <cuda_fp16.h>
#include <mma.h>
using namespace nvcuda;

#define NH 16
#define HD 64
#define BB 2
#define TT 2048
#define SS 2048
#define EE 1024
#define MM (BB * TT)   // 4096 rows

// Scratch (allocation-free: device globals). Layout [B*T, E] = [b,t,h,d].
__device__ float  g_q[MM * EE];
__device__ __half g_k[MM * EE];     // fp16, by gemm epilogue
__device__ __half g_v[MM * EE];     // fp16, by gemm epilogue
__device__ float  g_ctx[MM * EE];   // by attn epilogue
__device__ float  g_rowinv[BB * NH * TT];

// fp16 copies of GEMM inputs (halves traffic; same significand as tf32)
__device__ __half h_src[MM * EE];
__device__ __half h_tgt[MM * EE];
__device__ __half h_wq[EE * EE];
__device__ __half h_wk[EE * EE];
__device__ __half h_wv[EE * EE];
__device__ __half h_wo[EE * EE];
__device__ __half h_ctx[MM * EE];   // fp16 ctx for out-projection

// ---------------- helpers ----------------
__device__ __forceinline__ void cpa16(void* s, const void* g) {
    unsigned sa = (unsigned)__cvta_generic_to_shared(s);
    asm volatile("cp.async.ca.shared.global [%0], [%1], 16;\n" :: "r"(sa), "l"(g));
}
__device__ __forceinline__ void cp_commit() {
    asm volatile("cp.async.commit_group;\n");
}
template<int N> __device__ __forceinline__ void cp_wait() {
    asm volatile("cp.async.wait_group %0;\n" :: "n"(N));
}
__device__ __forceinline__ float ex2f(float x) {
    float y;
    asm("ex2.approx.f32 %0, %1;" : "=f"(y) : "f"(x));
    return y;
}
__device__ __forceinline__ void mma_f16(float* c, unsigned a0, unsigned a1,
                                        unsigned a2, unsigned a3,
                                        unsigned b0, unsigned b1) {
    asm volatile(
        "mma.sync.aligned.m16n8k16.row.col.f32.f16.f16.f32 "
        "{%0,%1,%2,%3},{%4,%5,%6,%7},{%8,%9},{%0,%1,%2,%3};"
        : "+f"(c[0]), "+f"(c[1]), "+f"(c[2]), "+f"(c[3])
        : "r"(a0), "r"(a1), "r"(a2), "r"(a3), "r"(b0), "r"(b1));
}
__device__ __forceinline__ void ldsm_x4(unsigned& r0, unsigned& r1,
                                        unsigned& r2, unsigned& r3, unsigned addr) {
    asm volatile("ldmatrix.sync.aligned.m8n8.x4.shared.b16 {%0,%1,%2,%3},[%4];"
                 : "=r"(r0), "=r"(r1), "=r"(r2), "=r"(r3) : "r"(addr));
}
__device__ __forceinline__ void ldsm_x4_t(unsigned& r0, unsigned& r1,
                                          unsigned& r2, unsigned& r3, unsigned addr) {
    asm volatile("ldmatrix.sync.aligned.m8n8.x4.trans.shared.b16 {%0,%1,%2,%3},[%4];"
                 : "=r"(r0), "=r"(r1), "=r"(r2), "=r"(r3) : "r"(addr));
}
__device__ __forceinline__ unsigned pack_h2(float lo, float hi) {
    __half2 h = __floats2half2_rn(lo, hi);
    return *(unsigned*)&h;
}

// ---------------------------------------------------------------------------
// Convert all 6 GEMM inputs fp32 -> fp16, one launch (grid.y selects array).
// ---------------------------------------------------------------------------
__global__ __launch_bounds__(256)
void convert_all_kernel(const float4* __restrict__ src, const float4* __restrict__ tgt,
                        const float4* __restrict__ wq, const float4* __restrict__ wk,
                        const float4* __restrict__ wv, const float4* __restrict__ wo)
{
    const float4* in;
    __half* out;
    int n4;
    switch (blockIdx.y) {
        case 0: in = src; out = h_src; n4 = MM * EE / 4; break;
        case 1: in = tgt; out = h_tgt; n4 = MM * EE / 4; break;
        case 2: in = wq;  out = h_wq;  n4 = EE * EE / 4; break;
        case 3: in = wk;  out = h_wk;  n4 = EE * EE / 4; break;
        case 4: in = wv;  out = h_wv;  n4 = EE * EE / 4; break;
        default: in = wo; out = h_wo;  n4 = EE * EE / 4; break;
    }
    int i = blockIdx.x * blockDim.x + threadIdx.x;
    int stride = gridDim.x * blockDim.x;
    for (; i < n4; i += stride) {
        float4 v = in[i];
        __half2 h0 = __floats2half2_rn(v.x, v.y);
        __half2 h1 = __floats2half2_rn(v.z, v.w);
        *(uint2*)(out + (size_t)i * 4) = make_uint2(*(unsigned*)&h0, *(unsigned*)&h1);
    }
}

// ---------------------------------------------------------------------------
// NT GEMM (fp16 WMMA, fp32 accum): C[M,N] = A[M,1024] * W[N,1024]^T
// BM=128, BN=128, BK=64, 256 threads, 4x2 warps, warp tile 32x64.
// 2-stage cp.async, 16 mainloop iters. 2 CTAs/SM.
// MODE: 0 = float out (Q), 2 = half out (K/V), 3 = float + bias (out proj),
//       4 = float out AND half out (ctx not needed; unused)
// ---------------------------------------------------------------------------

#define HLDA 72   // 64 + 8 halves pad (144 B rows; 16B-aligned, ldsm-friendly)

template<int MODE>
__device__ __forceinline__ void gemm_body(const __half* __restrict__ A,
                                          const __half* __restrict__ W,
                                          float* __restrict__ O,
                                          __half* __restrict__ Oh,
                                          const float* __restrict__ bo)
{
    __shared__ __align__(16) __half smem_all[4 * 128 * HLDA];   // 73728 B
    __half* As0 = smem_all;
    __half* As1 = smem_all + 128 * HLDA;
    __half* Ws0 = smem_all + 2 * 128 * HLDA;
    __half* Ws1 = smem_all + 3 * 128 * HLDA;

    const int tid = threadIdx.x;
    const int warp = tid >> 5;
    const int wm = warp >> 1;
    const int wn = warp & 1;
    const int m0 = blockIdx.y * 128;
    const int n0 = blockIdx.x * 128;

    wmma::fragment<wmma::accumulator, 16, 16, 16, float> acc[2][4];
#pragma unroll
    for (int i = 0; i < 2; i++)
#pragma unroll
        for (int j = 0; j < 4; j++) wmma::fill_fragment(acc[i][j], 0.0f);

    // tile loads: 128 rows x 64 halves = 1024 cpa16 -> 4 per thread
#pragma unroll
    for (int i = 0; i < 4; i++) {
        int e = tid + i * 256;
        int r = e >> 3, c = (e & 7) * 8;
        cpa16(As0 + r * HLDA + c, A + (size_t)(m0 + r) * 1024 + c);
        cpa16(Ws0 + r * HLDA + c, W + (size_t)(n0 + r) * 1024 + c);
    }
    cp_commit();

    for (int t = 0; t < 16; t++) {
        if (t < 15) {
            int k0 = (t + 1) * 64;
            __half* ad = ((t + 1) & 1) ? As1 : As0;
            __half* wd = ((t + 1) & 1) ? Ws1 : Ws0;
#pragma unroll
            for (int i = 0; i < 4; i++) {
                int e = tid + i * 256;
                int r = e >> 3, c = (e & 7) * 8;
                cpa16(ad + r * HLDA + c, A + (size_t)(m0 + r) * 1024 + k0 + c);
                cpa16(wd + r * HLDA + c, W + (size_t)(n0 + r) * 1024 + k0 + c);
            }
            cp_commit();
            cp_wait<1>();
        } else {
            cp_wait<0>();
        }
        __syncthreads();

        const __half* as = (t & 1) ? As1 : As0;
        const __half* ws = (t & 1) ? Ws1 : Ws0;
#pragma unroll
        for (int kk = 0; kk < 64; kk += 16) {
            wmma::fragment<wmma::matrix_a, 16, 16, 16, __half, wmma::row_major> af[2];
            wmma::fragment<wmma::matrix_b, 16, 16, 16, __half, wmma::col_major> bf[4];
#pragma unroll
            for (int i = 0; i < 2; i++)
                wmma::load_matrix_sync(af[i], as + (wm * 32 + i * 16) * HLDA + kk, HLDA);
#pragma unroll
            for (int j = 0; j < 4; j++)
                wmma::load_matrix_sync(bf[j], ws + (wn * 64 + j * 16) * HLDA + kk, HLDA);
#pragma unroll
            for (int i = 0; i < 2; i++)
#pragma unroll
                for (int j = 0; j < 4; j++)
                    wmma::mma_sync(acc[i][j], af[i], bf[j], acc[i][j]);
        }
        __syncthreads();
    }

    if (MODE == 3) {
        float* Cs = (float*)smem_all;    // 128 x 132 floats = 67584 B, fits
#pragma unroll
        for (int i = 0; i < 2; i++)
#pragma unroll
            for (int j = 0; j < 4; j++)
                wmma::store_matrix_sync(Cs + (wm * 32 + i * 16) * 132 + wn * 64 + j * 16,
                                        acc[i][j], 132, wmma::mem_row_major);
        __syncthreads();
#pragma unroll
        for (int i = 0; i < 16; i++) {
            int e = tid + i * 256;
            int r = e >> 5, c = (e & 31) * 4;
            float4 v = *(float4*)(Cs + r * 132 + c);
            float4 b4 = *(const float4*)(bo + n0 + c);
            v.x += b4.x; v.y += b4.y; v.z += b4.z; v.w += b4.w;
            *(float4*)(O + (size_t)(m0 + r) * EE + n0 + c) = v;
        }
    } else if (MODE == 2) {
        float* Cs = (float*)smem_all;
#pragma unroll
        for (int i = 0; i < 2; i++)
#pragma unroll
            for (int j = 0; j < 4; j++)
                wmma::store_matrix_sync(Cs + (wm * 32 + i * 16) * 132 + wn * 64 + j * 16,
                                        acc[i][j], 132, wmma::mem_row_major);
        __syncthreads();
#pragma unroll
        for (int i = 0; i < 16; i++) {
            int e = tid + i * 256;
            int r = e >> 5, c = (e & 31) * 4;
            float4 v = *(float4*)(Cs + r * 132 + c);
            __half2 h0 = __floats2half2_rn(v.x, v.y);
            __half2 h1 = __floats2half2_rn(v.z, v.w);
            *(uint2*)(Oh + (size_t)(m0 + r) * EE + n0 + c)
                = make_uint2(*(unsigned*)&h0, *(unsigned*)&h1);
        }
    } else {
#pragma unroll
        for (int i = 0; i < 2; i++)
#pragma unroll
            for (int j = 0; j < 4; j++)
                wmma::store_matrix_sync(
                    O + (size_t)(m0 + wm * 32 + i * 16) * 1024 + n0 + wn * 64 + j * 16,
                    acc[i][j], 1024, wmma::mem_row_major);
    }
}

__global__ __launch_bounds__(256, 2)
void gemm_qkv_kernel()
{
    const int z = blockIdx.z;
    if (z == 0)      gemm_body<0>(h_tgt, h_wq, g_q, nullptr, nullptr);
    else if (z == 1) gemm_body<2>(h_src, h_wk, nullptr, g_k, nullptr);
    else             gemm_body<2>(h_src, h_wv, nullptr, g_v, nullptr);
}

__global__ __launch_bounds__(256, 2)
void gemm_out_kernel(const float* __restrict__ bo, float* __restrict__ out)
{
    gemm_body<3>(h_ctx, h_wo, out, nullptr, bo);
}

// ---------------------------------------------------------------------------
// Attention, all-fp16 MMA, register-resident P, single pass over keys.
// (unchanged from R12 except ctx stored as fp16 for the fp16 out-projection)
// ---------------------------------------------------------------------------

#define KLD2 72  // K tile row stride (halves)
#define VLD 72   // V tile row stride (halves)
#define SLD 72   // staged attn tile row stride (floats)

__global__ __launch_bounds__(256, 2)
void attn_kernel(float* __restrict__ attn_out)
{
    extern __shared__ __align__(16) float sm[];
    __half* K0 = (__half*)sm;                   // 64*KLD2 halves
    __half* K1 = K0 + 64 * KLD2;
    __half* V0 = K1 + 64 * KLD2;                // 64*VLD halves
    __half* V1 = V0 + 64 * VLD;
    float*  Sb = (float*)(V1 + 64 * VLD);       // 128*SLD floats (staging)

    const int tid = threadIdx.x;
    const int warp = tid >> 5, lane = tid & 31;
    const int g = lane >> 2, tg = lane & 3;
    const int bh = blockIdx.y, b = bh >> 4, h = bh & 15;
    const int t0 = blockIdx.x * 128;

    const __half* kbase = g_k + (size_t)(b * SS) * EE + h * HD;
    const __half* vbase = g_v + (size_t)(b * SS) * EE + h * HD;

    // prologue: tile 0 (K+V fp16: 64 rows x 128B each)
#pragma unroll
    for (int i = 0; i < 2; i++) {
        int e = tid + i * 256, r = e >> 3, c = (e & 7) * 8;
        cpa16(K0 + r * KLD2 + c, kbase + (size_t)r * EE + c);
        cpa16(V0 + r * VLD + c, vbase + (size_t)r * EE + c);
    }
    cp_commit();

    // Q into fp16 regs: rows (t0+16w+g),(+8); a-frags per 16-hd k-block
    const float QSC = 1.44269504f * 0.125f;
    unsigned qh[4][4];
    {
        const float* qpA = g_q + (size_t)(b * TT + t0 + warp * 16 + g) * EE + h * HD;
        const float* qpB = qpA + (size_t)8 * EE;
#pragma unroll
        for (int kb = 0; kb < 4; kb++) {
            int c = kb * 16 + 2 * tg;
            qh[kb][0] = pack_h2(qpA[c] * QSC,     qpA[c + 1] * QSC);
            qh[kb][1] = pack_h2(qpB[c] * QSC,     qpB[c + 1] * QSC);
            qh[kb][2] = pack_h2(qpA[c + 8] * QSC, qpA[c + 9] * QSC);
            qh[kb][3] = pack_h2(qpB[c + 8] * QSC, qpB[c + 9] * QSC);
        }
    }

    float cacc[8][4];
#pragma unroll
    for (int j = 0; j < 8; j++)
#pragma unroll
        for (int x = 0; x < 4; x++) cacc[j][x] = 0.0f;
    float sumA = 0.0f, sumB = 0.0f;

    float* sbA = Sb + (warp * 16 + g) * SLD;
    float* sbB = sbA + 8 * SLD;

    const int k_keyoff = ((lane >> 4) << 3) + (lane & 7);
    const int k_hdoff = (lane & 8) ? 16 : 0;   // bytes

    for (int it = 0; it < 32; it++) {
        cp_wait<0>();
        __syncthreads();

        if (it + 1 < 32) {
            __half* Kd = (it & 1) ? K0 : K1;
            __half* Vd = (it & 1) ? V0 : V1;
            const __half* ksrc = kbase + (size_t)(it + 1) * 64 * EE;
            const __half* vsrc = vbase + (size_t)(it + 1) * 64 * EE;
#pragma unroll
            for (int i = 0; i < 2; i++) {
                int e = tid + i * 256, r = e >> 3, c = (e & 7) * 8;
                cpa16(Kd + r * KLD2 + c, ksrc + (size_t)r * EE + c);
                cpa16(Vd + r * VLD + c, vsrc + (size_t)r * EE + c);
            }
            cp_commit();
        }

        const __half* K = (it & 1) ? K1 : K0;
        const __half* V = (it & 1) ? V1 : V0;
        unsigned kaddr = (unsigned)__cvta_generic_to_shared(K)
                       + k_keyoff * (KLD2 * 2) + k_hdoff;
        unsigned vaddr = (unsigned)__cvta_generic_to_shared(
            V + (lane & 15) * VLD + (lane >> 4) * 8);

#pragma unroll
        for (int jg = 0; jg < 4; jg++) {
            float S0[4] = {0, 0, 0, 0}, S1[4] = {0, 0, 0, 0};
#pragma unroll
            for (int kb = 0; kb < 4; kb++) {
                unsigned b0, b1, b2, b3;
                ldsm_x4(b0, b1, b2, b3, kaddr + jg * (16 * KLD2 * 2) + kb * 32);
                mma_f16(S0, qh[kb][0], qh[kb][1], qh[kb][2], qh[kb][3], b0, b1);
                mma_f16(S1, qh[kb][0], qh[kb][1], qh[kb][2], qh[kb][3], b2, b3);
            }

            float p00 = ex2f(S0[0]), p01 = ex2f(S0[1]), p02 = ex2f(S0[2]), p03 = ex2f(S0[3]);
            float p10 = ex2f(S1[0]), p11 = ex2f(S1[1]), p12 = ex2f(S1[2]), p13 = ex2f(S1[3]);
            sumA += (p00 + p01) + (p10 + p11);
            sumB += (p02 + p03) + (p12 + p13);
            int col = jg * 16 + 2 * tg;
            *(float2*)(sbA + col)     = make_float2(p00, p01);
            *(float2*)(sbA + col + 8) = make_float2(p10, p11);
            *(float2*)(sbB + col)     = make_float2(p02, p03);
            *(float2*)(sbB + col + 8) = make_float2(p12, p13);

            unsigned pa0 = pack_h2(p00, p01);
            unsigned pa1 = pack_h2(p02, p03);
            unsigned pa2 = pack_h2(p10, p11);
            unsigned pa3 = pack_h2(p12, p13);

#pragma unroll
            for (int ng = 0; ng < 4; ng++) {
                unsigned b0, b1, b2, b3;
                ldsm_x4_t(b0, b1, b2, b3, vaddr + jg * (16 * VLD * 2) + ng * 32);
                mma_f16(cacc[2 * ng],     pa0, pa1, pa2, pa3, b0, b1);
                mma_f16(cacc[2 * ng + 1], pa0, pa1, pa2, pa3, b2, b3);
            }
        }

        __syncthreads();   // exp tile fully staged
#pragma unroll
        for (int j = 0; j < 8; j++) {
            int e = tid + j * 256;
            int r = e >> 4, c = (e & 15) * 4;
            float4 v = *(float4*)(Sb + r * SLD + c);
            *(float4*)(attn_out + (size_t)(bh * TT + t0 + r) * SS + it * 64 + c) = v;
        }
    }

    // rowsum reduce within quad
    sumA += __shfl_xor_sync(0xffffffffu, sumA, 1);
    sumA += __shfl_xor_sync(0xffffffffu, sumA, 2);
    sumB += __shfl_xor_sync(0xffffffffu, sumB, 1);
    sumB += __shfl_xor_sync(0xffffffffu, sumB, 2);
    float invA = 1.0f / sumA, invB = 1.0f / sumB;
    if (tg == 0) {
        g_rowinv[bh * TT + t0 + warp * 16 + g] = invA;
        g_rowinv[bh * TT + t0 + warp * 16 + 8 + g] = invB;
    }

    // ctx: normalize, store fp16 (out-projection GEMM is fp16)
    __half* cA = h_ctx + (size_t)(b * TT + t0 + warp * 16 + g) * EE + h * HD + 2 * tg;
    __half* cB = cA + (size_t)8 * EE;
#pragma unroll
    for (int jn = 0; jn < 8; jn++) {
        *(unsigned*)(cA + 8 * jn) = pack_h2(cacc[jn][0] * invA, cacc[jn][1] * invA);
        *(unsigned*)(cB + 8 * jn) = pack_h2(cacc[jn][2] * invB, cacc[jn][3] * invB);
    }
}

// ---------------------------------------------------------------------------
// Streaming rescale: attn *= rowinv[row]. Pure bandwidth (1.07 GB).
// ---------------------------------------------------------------------------

__global__ __launch_bounds__(256)
void rescale_kernel(float* __restrict__ attn)
{
    const size_t n4 = (size_t)BB * NH * TT * SS / 4;
    size_t i = (size_t)blockIdx.x * blockDim.x + threadIdx.x;
    const size_t stride = (size_t)gridDim.x * blockDim.x;
    float4* a4 = (float4*)attn;
    for (; i < n4; i += stride) {
        float inv = __ldg(&g_rowinv[i >> 9]);
        float4 v = a4[i];
        v.x *= inv; v.y *= inv; v.z *= inv; v.w *= inv;
        a4[i] = v;
    }
}

// ---------------------------------------------------------------------------

extern "C" void kernel_launch(void* const* d_in, const int* in_sizes, int n_in,
                              void* d_out, int out_size)
{
    const float* src = (const float*)d_in[0];
    const float* tgt = (const float*)d_in[1];
    const float* Wq  = (const float*)d_in[2];
    const float* Wk  = (const float*)d_in[3];
    const float* Wv  = (const float*)d_in[4];
    const float* Wo  = (const float*)d_in[5];
    const float* bo  = (const float*)d_in[6];

    float* out  = (float*)d_out;                  // [2,2048,1024]
    float* attn = out + (size_t)MM * EE;          // [2,16,2048,2048]

    const int attn_smem = (2 * 64 * KLD2 + 2 * 64 * VLD) * 2 + 128 * SLD * 4;  // 73728 B
    cudaFuncSetAttribute(attn_kernel, cudaFuncAttributeMaxDynamicSharedMemorySize, attn_smem);

    // convert all GEMM inputs to fp16, one launch
    dim3 gr(512, 6);
    convert_all_kernel<<<gr, 256>>>((const float4*)src, (const float4*)tgt,
                                    (const float4*)Wq, (const float4*)Wk,
                                    (const float4*)Wv, (const float4*)Wo);

    dim3 g1(8, 32, 3);
    gemm_qkv_kernel<<<g1, 256>>>();

    dim3 g2(16, 32);
    attn_kernel<<<g2, 256, attn_smem>>>(attn);

    dim3 g3(8, 32);
    gemm_out_kernel<<<g3, 256>>>(bo, out);

    rescale_kernel<<<8192, 256>>>(attn);
}

// round 16
// speedup vs baseline: 2.9251x; 1.2561x over previous
#include <cuda_runtime.h>
#include <cuda_fp16.h>
#include <mma.h>
using namespace nvcuda;

#define NH 16
#define HD 64
#define BB 2
#define TT 2048
#define SS 2048
#define EE 1024
#define MM (BB * TT)   // 4096 rows

// Scratch (allocation-free: device globals). Layout [B*T, E] = [b,t,h,d].
__device__ float  g_q[MM * EE];
__device__ __half g_k[MM * EE];     // fp16, by gemm epilogue
__device__ __half g_v[MM * EE];     // fp16, by gemm epilogue

// fp16 copies of GEMM inputs (halves traffic; same significand as tf32)
__device__ __half h_src[MM * EE];
__device__ __half h_tgt[MM * EE];
__device__ __half h_wq[EE * EE];
__device__ __half h_wk[EE * EE];
__device__ __half h_wv[EE * EE];
__device__ __half h_wo[EE * EE];
__device__ __half h_ctx[MM * EE];   // fp16 ctx for out-projection

// ---------------- helpers ----------------
__device__ __forceinline__ void cpa16(void* s, const void* g) {
    unsigned sa = (unsigned)__cvta_generic_to_shared(s);
    asm volatile("cp.async.ca.shared.global [%0], [%1], 16;\n" :: "r"(sa), "l"(g));
}
__device__ __forceinline__ void cp_commit() {
    asm volatile("cp.async.commit_group;\n");
}
template<int N> __device__ __forceinline__ void cp_wait() {
    asm volatile("cp.async.wait_group %0;\n" :: "n"(N));
}
__device__ __forceinline__ float ex2f(float x) {
    float y;
    asm("ex2.approx.f32 %0, %1;" : "=f"(y) : "f"(x));
    return y;
}
__device__ __forceinline__ void mma_f16(float* c, unsigned a0, unsigned a1,
                                        unsigned a2, unsigned a3,
                                        unsigned b0, unsigned b1) {
    asm volatile(
        "mma.sync.aligned.m16n8k16.row.col.f32.f16.f16.f32 "
        "{%0,%1,%2,%3},{%4,%5,%6,%7},{%8,%9},{%0,%1,%2,%3};"
        : "+f"(c[0]), "+f"(c[1]), "+f"(c[2]), "+f"(c[3])
        : "r"(a0), "r"(a1), "r"(a2), "r"(a3), "r"(b0), "r"(b1));
}
__device__ __forceinline__ void ldsm_x4(unsigned& r0, unsigned& r1,
                                        unsigned& r2, unsigned& r3, unsigned addr) {
    asm volatile("ldmatrix.sync.aligned.m8n8.x4.shared.b16 {%0,%1,%2,%3},[%4];"
                 : "=r"(r0), "=r"(r1), "=r"(r2), "=r"(r3) : "r"(addr));
}
__device__ __forceinline__ void ldsm_x4_t(unsigned& r0, unsigned& r1,
                                          unsigned& r2, unsigned& r3, unsigned addr) {
    asm volatile("ldmatrix.sync.aligned.m8n8.x4.trans.shared.b16 {%0,%1,%2,%3},[%4];"
                 : "=r"(r0), "=r"(r1), "=r"(r2), "=r"(r3) : "r"(addr));
}
__device__ __forceinline__ unsigned pack_h2(float lo, float hi) {
    __half2 h = __floats2half2_rn(lo, hi);
    return *(unsigned*)&h;
}

// ---------------------------------------------------------------------------
// Convert all 6 GEMM inputs fp32 -> fp16, one launch (grid.y selects array).
// ---------------------------------------------------------------------------
__global__ __launch_bounds__(256)
void convert_all_kernel(const float4* __restrict__ src, const float4* __restrict__ tgt,
                        const float4* __restrict__ wq, const float4* __restrict__ wk,
                        const float4* __restrict__ wv, const float4* __restrict__ wo)
{
    const float4* in;
    __half* out;
    int n4;
    switch (blockIdx.y) {
        case 0: in = src; out = h_src; n4 = MM * EE / 4; break;
        case 1: in = tgt; out = h_tgt; n4 = MM * EE / 4; break;
        case 2: in = wq;  out = h_wq;  n4 = EE * EE / 4; break;
        case 3: in = wk;  out = h_wk;  n4 = EE * EE / 4; break;
        case 4: in = wv;  out = h_wv;  n4 = EE * EE / 4; break;
        default: in = wo; out = h_wo;  n4 = EE * EE / 4; break;
    }
    int i = blockIdx.x * blockDim.x + threadIdx.x;
    int stride = gridDim.x * blockDim.x;
    for (; i < n4; i += stride) {
        float4 v = in[i];
        __half2 h0 = __floats2half2_rn(v.x, v.y);
        __half2 h1 = __floats2half2_rn(v.z, v.w);
        *(uint2*)(out + (size_t)i * 4) = make_uint2(*(unsigned*)&h0, *(unsigned*)&h1);
    }
}

// ---------------------------------------------------------------------------
// NT GEMM (fp16 WMMA, fp32 accum): C[M,N] = A[M,1024] * W[N,1024]^T
// BM=128, BN=128, BK=64, 256 threads, 4x2 warps, warp tile 32x64.
// 2-stage cp.async, 16 mainloop iters. 2 CTAs/SM.
// MODE: 0 = float out (Q), 2 = half out (K/V), 3 = float + bias (out proj)
// ---------------------------------------------------------------------------

#define HLDA 72   // 64 + 8 halves pad

template<int MODE>
__device__ __forceinline__ void gemm_body(const __half* __restrict__ A,
                                          const __half* __restrict__ W,
                                          float* __restrict__ O,
                                          __half* __restrict__ Oh,
                                          const float* __restrict__ bo)
{
    __shared__ __align__(16) __half smem_all[4 * 128 * HLDA];   // 73728 B
    __half* As0 = smem_all;
    __half* As1 = smem_all + 128 * HLDA;
    __half* Ws0 = smem_all + 2 * 128 * HLDA;
    __half* Ws1 = smem_all + 3 * 128 * HLDA;

    const int tid = threadIdx.x;
    const int warp = tid >> 5;
    const int wm = warp >> 1;
    const int wn = warp & 1;
    const int m0 = blockIdx.y * 128;
    const int n0 = blockIdx.x * 128;

    wmma::fragment<wmma::accumulator, 16, 16, 16, float> acc[2][4];
#pragma unroll
    for (int i = 0; i < 2; i++)
#pragma unroll
        for (int j = 0; j < 4; j++) wmma::fill_fragment(acc[i][j], 0.0f);

#pragma unroll
    for (int i = 0; i < 4; i++) {
        int e = tid + i * 256;
        int r = e >> 3, c = (e & 7) * 8;
        cpa16(As0 + r * HLDA + c, A + (size_t)(m0 + r) * 1024 + c);
        cpa16(Ws0 + r * HLDA + c, W + (size_t)(n0 + r) * 1024 + c);
    }
    cp_commit();

    for (int t = 0; t < 16; t++) {
        if (t < 15) {
            int k0 = (t + 1) * 64;
            __half* ad = ((t + 1) & 1) ? As1 : As0;
            __half* wd = ((t + 1) & 1) ? Ws1 : Ws0;
#pragma unroll
            for (int i = 0; i < 4; i++) {
                int e = tid + i * 256;
                int r = e >> 3, c = (e & 7) * 8;
                cpa16(ad + r * HLDA + c, A + (size_t)(m0 + r) * 1024 + k0 + c);
                cpa16(wd + r * HLDA + c, W + (size_t)(n0 + r) * 1024 + k0 + c);
            }
            cp_commit();
            cp_wait<1>();
        } else {
            cp_wait<0>();
        }
        __syncthreads();

        const __half* as = (t & 1) ? As1 : As0;
        const __half* ws = (t & 1) ? Ws1 : Ws0;
#pragma unroll
        for (int kk = 0; kk < 64; kk += 16) {
            wmma::fragment<wmma::matrix_a, 16, 16, 16, __half, wmma::row_major> af[2];
            wmma::fragment<wmma::matrix_b, 16, 16, 16, __half, wmma::col_major> bf[4];
#pragma unroll
            for (int i = 0; i < 2; i++)
                wmma::load_matrix_sync(af[i], as + (wm * 32 + i * 16) * HLDA + kk, HLDA);
#pragma unroll
            for (int j = 0; j < 4; j++)
                wmma::load_matrix_sync(bf[j], ws + (wn * 64 + j * 16) * HLDA + kk, HLDA);
#pragma unroll
            for (int i = 0; i < 2; i++)
#pragma unroll
                for (int j = 0; j < 4; j++)
                    wmma::mma_sync(acc[i][j], af[i], bf[j], acc[i][j]);
        }
        __syncthreads();
    }

    if (MODE == 3) {
        float* Cs = (float*)smem_all;    // 128 x 132 floats
#pragma unroll
        for (int i = 0; i < 2; i++)
#pragma unroll
            for (int j = 0; j < 4; j++)
                wmma::store_matrix_sync(Cs + (wm * 32 + i * 16) * 132 + wn * 64 + j * 16,
                                        acc[i][j], 132, wmma::mem_row_major);
        __syncthreads();
#pragma unroll
        for (int i = 0; i < 16; i++) {
            int e = tid + i * 256;
            int r = e >> 5, c = (e & 31) * 4;
            float4 v = *(float4*)(Cs + r * 132 + c);
            float4 b4 = *(const float4*)(bo + n0 + c);
            v.x += b4.x; v.y += b4.y; v.z += b4.z; v.w += b4.w;
            *(float4*)(O + (size_t)(m0 + r) * EE + n0 + c) = v;
        }
    } else if (MODE == 2) {
        float* Cs = (float*)smem_all;
#pragma unroll
        for (int i = 0; i < 2; i++)
#pragma unroll
            for (int j = 0; j < 4; j++)
                wmma::store_matrix_sync(Cs + (wm * 32 + i * 16) * 132 + wn * 64 + j * 16,
                                        acc[i][j], 132, wmma::mem_row_major);
        __syncthreads();
#pragma unroll
        for (int i = 0; i < 16; i++) {
            int e = tid + i * 256;
            int r = e >> 5, c = (e & 31) * 4;
            float4 v = *(float4*)(Cs + r * 132 + c);
            __half2 h0 = __floats2half2_rn(v.x, v.y);
            __half2 h1 = __floats2half2_rn(v.z, v.w);
            *(uint2*)(Oh + (size_t)(m0 + r) * EE + n0 + c)
                = make_uint2(*(unsigned*)&h0, *(unsigned*)&h1);
        }
    } else {
#pragma unroll
        for (int i = 0; i < 2; i++)
#pragma unroll
            for (int j = 0; j < 4; j++)
                wmma::store_matrix_sync(
                    O + (size_t)(m0 + wm * 32 + i * 16) * 1024 + n0 + wn * 64 + j * 16,
                    acc[i][j], 1024, wmma::mem_row_major);
    }
}

__global__ __launch_bounds__(256, 2)
void gemm_qkv_kernel()
{
    const int z = blockIdx.z;
    if (z == 0)      gemm_body<0>(h_tgt, h_wq, g_q, nullptr, nullptr);
    else if (z == 1) gemm_body<2>(h_src, h_wk, nullptr, g_k, nullptr);
    else             gemm_body<2>(h_src, h_wv, nullptr, g_v, nullptr);
}

__global__ __launch_bounds__(256, 2)
void gemm_out_kernel(const float* __restrict__ bo, float* __restrict__ out)
{
    gemm_body<3>(h_ctx, h_wo, out, nullptr, bo);
}

// ---------------------------------------------------------------------------
// Attention, TWO-PHASE, all-fp16 MMA, register-resident P.
// Pass 1: K-only, QK + exp -> rowsums (registers). No stores.
// Pass 2: recompute S (bit-identical), p = exp2(s)*inv, write NORMALIZED
//         attn (staged smem -> coalesced STG), PV with normalized p.
// No rescale kernel, no rowinv globals. Per-warp rows own their inv in regs.
// ---------------------------------------------------------------------------

#define KLD2 72  // K tile row stride (halves)
#define VLD 72   // V tile row stride (halves)
#define SLD 72   // staged attn tile row stride (floats)

__global__ __launch_bounds__(256, 2)
void attn_kernel(float* __restrict__ attn_out)
{
    extern __shared__ __align__(16) float sm[];
    __half* K0 = (__half*)sm;                   // 64*KLD2 halves
    __half* K1 = K0 + 64 * KLD2;
    __half* V0 = K1 + 64 * KLD2;                // 64*VLD halves
    __half* V1 = V0 + 64 * VLD;
    float*  Sb = (float*)(V1 + 64 * VLD);       // 128*SLD floats (staging)

    const int tid = threadIdx.x;
    const int warp = tid >> 5, lane = tid & 31;
    const int g = lane >> 2, tg = lane & 3;
    const int bh = blockIdx.y, b = bh >> 4, h = bh & 15;
    const int t0 = blockIdx.x * 128;

    const __half* kbase = g_k + (size_t)(b * SS) * EE + h * HD;
    const __half* vbase = g_v + (size_t)(b * SS) * EE + h * HD;

    // pass-1 prologue: K tile 0 only
#pragma unroll
    for (int i = 0; i < 2; i++) {
        int e = tid + i * 256, r = e >> 3, c = (e & 7) * 8;
        cpa16(K0 + r * KLD2 + c, kbase + (size_t)r * EE + c);
    }
    cp_commit();

    // Q into fp16 regs (scaled to base-2 domain)
    const float QSC = 1.44269504f * 0.125f;
    unsigned qh[4][4];
    {
        const float* qpA = g_q + (size_t)(b * TT + t0 + warp * 16 + g) * EE + h * HD;
        const float* qpB = qpA + (size_t)8 * EE;
#pragma unroll
        for (int kb = 0; kb < 4; kb++) {
            int c = kb * 16 + 2 * tg;
            qh[kb][0] = pack_h2(qpA[c] * QSC,     qpA[c + 1] * QSC);
            qh[kb][1] = pack_h2(qpB[c] * QSC,     qpB[c + 1] * QSC);
            qh[kb][2] = pack_h2(qpA[c + 8] * QSC, qpA[c + 9] * QSC);
            qh[kb][3] = pack_h2(qpB[c + 8] * QSC, qpB[c + 9] * QSC);
        }
    }

    const int k_keyoff = ((lane >> 4) << 3) + (lane & 7);
    const int k_hdoff = (lane & 8) ? 16 : 0;   // bytes

    // =================== pass 1: rowsums ===================
    float sumA = 0.0f, sumB = 0.0f;
    for (int it = 0; it < 32; it++) {
        cp_wait<0>();
        __syncthreads();

        if (it + 1 < 32) {
            __half* Kd = (it & 1) ? K0 : K1;
            const __half* ksrc = kbase + (size_t)(it + 1) * 64 * EE;
#pragma unroll
            for (int i = 0; i < 2; i++) {
                int e = tid + i * 256, r = e >> 3, c = (e & 7) * 8;
                cpa16(Kd + r * KLD2 + c, ksrc + (size_t)r * EE + c);
            }
            cp_commit();
        }

        const __half* K = (it & 1) ? K1 : K0;
        unsigned kaddr = (unsigned)__cvta_generic_to_shared(K)
                       + k_keyoff * (KLD2 * 2) + k_hdoff;

#pragma unroll
        for (int jg = 0; jg < 4; jg++) {
            float S0[4] = {0, 0, 0, 0}, S1[4] = {0, 0, 0, 0};
#pragma unroll
            for (int kb = 0; kb < 4; kb++) {
                unsigned b0, b1, b2, b3;
                ldsm_x4(b0, b1, b2, b3, kaddr + jg * (16 * KLD2 * 2) + kb * 32);
                mma_f16(S0, qh[kb][0], qh[kb][1], qh[kb][2], qh[kb][3], b0, b1);
                mma_f16(S1, qh[kb][0], qh[kb][1], qh[kb][2], qh[kb][3], b2, b3);
            }
            sumA += (ex2f(S0[0]) + ex2f(S0[1])) + (ex2f(S1[0]) + ex2f(S1[1]));
            sumB += (ex2f(S0[2]) + ex2f(S0[3])) + (ex2f(S1[2]) + ex2f(S1[3]));
        }
    }

    // reduce within quad (lanes tg=0..3 share rows); inv stays in registers
    sumA += __shfl_xor_sync(0xffffffffu, sumA, 1);
    sumA += __shfl_xor_sync(0xffffffffu, sumA, 2);
    sumB += __shfl_xor_sync(0xffffffffu, sumB, 1);
    sumB += __shfl_xor_sync(0xffffffffu, sumB, 2);
    const float invA = 1.0f / sumA, invB = 1.0f / sumB;

    // =================== pass 2: normalized write + PV ===================
    // prologue: K+V tile 0 (safe: writes K0/V0; stragglers read K1 in it=31)
#pragma unroll
    for (int i = 0; i < 2; i++) {
        int e = tid + i * 256, r = e >> 3, c = (e & 7) * 8;
        cpa16(K0 + r * KLD2 + c, kbase + (size_t)r * EE + c);
        cpa16(V0 + r * VLD + c, vbase + (size_t)r * EE + c);
    }
    cp_commit();

    float cacc[8][4];
#pragma unroll
    for (int j = 0; j < 8; j++)
#pragma unroll
        for (int x = 0; x < 4; x++) cacc[j][x] = 0.0f;

    float* sbA = Sb + (warp * 16 + g) * SLD;
    float* sbB = sbA + 8 * SLD;

    for (int it = 0; it < 32; it++) {
        cp_wait<0>();
        __syncthreads();

        if (it + 1 < 32) {
            __half* Kd = (it & 1) ? K0 : K1;
            __half* Vd = (it & 1) ? V0 : V1;
            const __half* ksrc = kbase + (size_t)(it + 1) * 64 * EE;
            const __half* vsrc = vbase + (size_t)(it + 1) * 64 * EE;
#pragma unroll
            for (int i = 0; i < 2; i++) {
                int e = tid + i * 256, r = e >> 3, c = (e & 7) * 8;
                cpa16(Kd + r * KLD2 + c, ksrc + (size_t)r * EE + c);
                cpa16(Vd + r * VLD + c, vsrc + (size_t)r * EE + c);
            }
            cp_commit();
        }

        const __half* K = (it & 1) ? K1 : K0;
        const __half* V = (it & 1) ? V1 : V0;
        unsigned kaddr = (unsigned)__cvta_generic_to_shared(K)
                       + k_keyoff * (KLD2 * 2) + k_hdoff;
        unsigned vaddr = (unsigned)__cvta_generic_to_shared(
            V + (lane & 15) * VLD + (lane >> 4) * 8);

#pragma unroll
        for (int jg = 0; jg < 4; jg++) {
            float S0[4] = {0, 0, 0, 0}, S1[4] = {0, 0, 0, 0};
#pragma unroll
            for (int kb = 0; kb < 4; kb++) {
                unsigned b0, b1, b2, b3;
                ldsm_x4(b0, b1, b2, b3, kaddr + jg * (16 * KLD2 * 2) + kb * 32);
                mma_f16(S0, qh[kb][0], qh[kb][1], qh[kb][2], qh[kb][3], b0, b1);
                mma_f16(S1, qh[kb][0], qh[kb][1], qh[kb][2], qh[kb][3], b2, b3);
            }

            // NORMALIZED p (S identical to pass 1 -> exact softmax)
            float p00 = ex2f(S0[0]) * invA, p01 = ex2f(S0[1]) * invA;
            float p02 = ex2f(S0[2]) * invB, p03 = ex2f(S0[3]) * invB;
            float p10 = ex2f(S1[0]) * invA, p11 = ex2f(S1[1]) * invA;
            float p12 = ex2f(S1[2]) * invB, p13 = ex2f(S1[3]) * invB;
            int col = jg * 16 + 2 * tg;
            *(float2*)(sbA + col)     = make_float2(p00, p01);
            *(float2*)(sbA + col + 8) = make_float2(p10, p11);
            *(float2*)(sbB + col)     = make_float2(p02, p03);
            *(float2*)(sbB + col + 8) = make_float2(p12, p13);

            unsigned pa0 = pack_h2(p00, p01);
            unsigned pa1 = pack_h2(p02, p03);
            unsigned pa2 = pack_h2(p10, p11);
            unsigned pa3 = pack_h2(p12, p13);

#pragma unroll
            for (int ng = 0; ng < 4; ng++) {
                unsigned b0, b1, b2, b3;
                ldsm_x4_t(b0, b1, b2, b3, vaddr + jg * (16 * VLD * 2) + ng * 32);
                mma_f16(cacc[2 * ng],     pa0, pa1, pa2, pa3, b0, b1);
                mma_f16(cacc[2 * ng + 1], pa0, pa1, pa2, pa3, b2, b3);
            }
        }

        __syncthreads();   // exp tile fully staged
        // coalesced STG: 16 lanes per row -> 2 rows per warp-instr -> 4 lines
#pragma unroll
        for (int j = 0; j < 8; j++) {
            int e = tid + j * 256;
            int r = e >> 4, c = (e & 15) * 4;
            float4 v = *(float4*)(Sb + r * SLD + c);
            *(float4*)(attn_out + (size_t)(bh * TT + t0 + r) * SS + it * 64 + c) = v;
        }
    }

    // ctx: already normalized; store fp16 for the fp16 out-projection
    __half* cA = h_ctx + (size_t)(b * TT + t0 + warp * 16 + g) * EE + h * HD + 2 * tg;
    __half* cB = cA + (size_t)8 * EE;
#pragma unroll
    for (int jn = 0; jn < 8; jn++) {
        *(unsigned*)(cA + 8 * jn) = pack_h2(cacc[jn][0], cacc[jn][1]);
        *(unsigned*)(cB + 8 * jn) = pack_h2(cacc[jn][2], cacc[jn][3]);
    }
}

// ---------------------------------------------------------------------------

extern "C" void kernel_launch(void* const* d_in, const int* in_sizes, int n_in,
                              void* d_out, int out_size)
{
    const float* src = (const float*)d_in[0];
    const float* tgt = (const float*)d_in[1];
    const float* Wq  = (const float*)d_in[2];
    const float* Wk  = (const float*)d_in[3];
    const float* Wv  = (const float*)d_in[4];
    const float* Wo  = (const float*)d_in[5];
    const float* bo  = (const float*)d_in[6];

    float* out  = (float*)d_out;                  // [2,2048,1024]
    float* attn = out + (size_t)MM * EE;          // [2,16,2048,2048]

    const int attn_smem = (2 * 64 * KLD2 + 2 * 64 * VLD) * 2 + 128 * SLD * 4;  // 73728 B
    cudaFuncSetAttribute(attn_kernel, cudaFuncAttributeMaxDynamicSharedMemorySize, attn_smem);

    // convert all GEMM inputs to fp16, one launch
    dim3 gr(512, 6);
    convert_all_kernel<<<gr, 256>>>((const float4*)src, (const float4*)tgt,
                                    (const float4*)Wq, (const float4*)Wk,
                                    (const float4*)Wv, (const float4*)Wo);

    dim3 g1(8, 32, 3);
    gemm_qkv_kernel<<<g1, 256>>>();

    dim3 g2(16, 32);
    attn_kernel<<<g2, 256, attn_smem>>>(attn);

    dim3 g3(8, 32);
    gemm_out_kernel<<<g3, 256>>>(bo, out);
}